// round 2
// baseline (speedup 1.0000x reference)
#include <cuda_runtime.h>
#include <math.h>

// ---------------------------------------------------------------------------
// Problem constants
// ---------------------------------------------------------------------------
constexpr int B_  = 32;
constexpr int L_  = 256;
constexpr int D_  = 256;
constexpr int E_  = 32;
constexpr int H_  = 8;
constexpr int HD_ = 32;
constexpr float SCALE_ = 0.17677669529663687f;  // 1/sqrt(32)

constexpr int ROWS_ = B_ * L_;   // 8192

// ---------------------------------------------------------------------------
// Device scratch
// ---------------------------------------------------------------------------
__device__ float g_qkv[ROWS_ * 3 * D_];   // [B*L, 768]  q|k|v
__device__ float g_aout[ROWS_ * D_];      // [B*L, 256]

// ---------------------------------------------------------------------------
// Kernel 1/3: C = A @ W^T + bias (unchanged, proven)
// ---------------------------------------------------------------------------
template<int BM, int BN, int BK>
__global__ __launch_bounds__(256)
void sgemm_nt_bias(const float* __restrict__ A, const float* __restrict__ W,
                   const float* __restrict__ bias, float* __restrict__ C,
                   int M, int N, int K)
{
    __shared__ float As[BK][BM + 4];
    __shared__ float Bs[BK][BN + 4];

    const int tid = threadIdx.x;
    const int tx  = tid & 15;
    const int ty  = tid >> 4;
    const int m0  = blockIdx.y * BM;
    const int n0  = blockIdx.x * BN;

    float acc[8][8];
#pragma unroll
    for (int i = 0; i < 8; i++)
#pragma unroll
        for (int j = 0; j < 8; j++) acc[i][j] = 0.f;

    for (int k0 = 0; k0 < K; k0 += BK) {
#pragma unroll
        for (int it = 0; it < (BM * BK) / (256 * 4); ++it) {
            int f4  = tid + it * 256;
            int row = f4 >> 2;
            int c4  = (f4 & 3) * 4;
            float4 v = *(const float4*)&A[(size_t)(m0 + row) * K + k0 + c4];
            As[c4 + 0][row] = v.x; As[c4 + 1][row] = v.y;
            As[c4 + 2][row] = v.z; As[c4 + 3][row] = v.w;
        }
#pragma unroll
        for (int it = 0; it < (BN * BK) / (256 * 4); ++it) {
            int f4  = tid + it * 256;
            int row = f4 >> 2;
            int c4  = (f4 & 3) * 4;
            float4 v = *(const float4*)&W[(size_t)(n0 + row) * K + k0 + c4];
            Bs[c4 + 0][row] = v.x; Bs[c4 + 1][row] = v.y;
            Bs[c4 + 2][row] = v.z; Bs[c4 + 3][row] = v.w;
        }
        __syncthreads();

#pragma unroll
        for (int kk = 0; kk < BK; ++kk) {
            float a[8], b[8];
            *(float4*)&a[0] = *(const float4*)&As[kk][ty * 8];
            *(float4*)&a[4] = *(const float4*)&As[kk][ty * 8 + 4];
            *(float4*)&b[0] = *(const float4*)&Bs[kk][tx * 8];
            *(float4*)&b[4] = *(const float4*)&Bs[kk][tx * 8 + 4];
#pragma unroll
            for (int i = 0; i < 8; i++)
#pragma unroll
                for (int j = 0; j < 8; j++)
                    acc[i][j] += a[i] * b[j];
        }
        __syncthreads();
    }

#pragma unroll
    for (int i = 0; i < 8; i++) {
        int m = m0 + ty * 8 + i;
#pragma unroll
        for (int j4 = 0; j4 < 2; j4++) {
            int n = n0 + tx * 8 + j4 * 4;
            float4 o;
            o.x = acc[i][j4 * 4 + 0] + bias[n + 0];
            o.y = acc[i][j4 * 4 + 1] + bias[n + 1];
            o.z = acc[i][j4 * 4 + 2] + bias[n + 2];
            o.w = acc[i][j4 * 4 + 3] + bias[n + 3];
            *(float4*)&C[(size_t)m * N + n] = o;
        }
    }
}

// ---------------------------------------------------------------------------
// cp.async helpers
// ---------------------------------------------------------------------------
__device__ __forceinline__ void cp_async16(void* smem_dst, const void* gmem_src) {
    unsigned s = (unsigned)__cvta_generic_to_shared(smem_dst);
    asm volatile("cp.async.cg.shared.global [%0], [%1], 16;\n" :: "r"(s), "l"(gmem_src));
}
__device__ __forceinline__ void cp_commit() {
    asm volatile("cp.async.commit_group;\n");
}
__device__ __forceinline__ void cp_wait1() {
    asm volatile("cp.async.wait_group 1;\n");
}

// ---------------------------------------------------------------------------
// Kernel 2: fused edge attention (pipelined v2)
// ---------------------------------------------------------------------------
constexpr int QT = 16;
constexpr int KT = 16;
constexpr int QSTR = D_ + 4;     // 260 (conflict-free LDS.128 phases)
constexpr int SSTR = KT + 4;     // 20 (16B-aligned rows)

struct AttnSmem {
    float q[QT][QSTR];           // 16.6 KB
    float k[2][KT][QSTR];        // 33.3 KB (double buffered, cp.async)
    float s[H_][QT][SSTR];       // raw scores -> p*g
    float g[H_][QT][SSTR];       // sigmoid gate
    float m[H_][QT];
    float z[H_][QT];
    float r[H_][QT];
    float ew[H_][E_];
    float gw[H_][E_];
    float eow[E_][H_];
    float eb[H_];
    float gb[H_];
    float eob[E_];
};

__global__ __launch_bounds__(256, 2)
void edge_attn_kernel(const float* __restrict__ edge_x,
                      const float* __restrict__ e_w, const float* __restrict__ e_b,
                      const float* __restrict__ g_w, const float* __restrict__ g_b,
                      const float* __restrict__ eo_w, const float* __restrict__ eo_b,
                      float* __restrict__ edge_out)
{
    extern __shared__ char smem_raw[];
    AttnSmem& sm = *reinterpret_cast<AttnSmem*>(smem_raw);

    const int tid = threadIdx.x;
    const int b   = blockIdx.y;
    const int q0  = blockIdx.x * QT;
    const size_t bL = (size_t)b * L_;

    // --- weights / state init ---
    ((float*)sm.ew)[tid]  = e_w[tid];
    ((float*)sm.gw)[tid]  = g_w[tid];
    ((float*)sm.eow)[tid] = eo_w[tid];
    if (tid < H_) { sm.eb[tid] = e_b[tid]; sm.gb[tid] = g_b[tid]; }
    if (tid < E_) { sm.eob[tid] = eo_b[tid]; }
    if (tid < H_ * QT) {
        ((float*)sm.m)[tid] = -1e30f;
        ((float*)sm.z)[tid] = 0.f;
    }

    // --- q tile (direct load) ---
#pragma unroll
    for (int it = 0; it < 4; ++it) {
        int f4  = tid + it * 256;
        int row = f4 >> 6;
        int c   = (f4 & 63) * 4;
        *(float4*)&sm.q[row][c] =
            *(const float4*)&g_qkv[(bL + q0 + row) * (3 * D_) + c];
    }

    const int qi   = tid >> 4;   // phase A query
    const int kk   = tid & 15;   // phase A key
    const int h    = tid >> 5;   // phase B head
    const int lane = tid & 31;

    // --- prologue: cp.async k tile 0 (group 0), prefetch edge vec tile 0 ---
    {
#pragma unroll
        for (int it = 0; it < 4; ++it) {
            int f4  = tid + it * 256;
            int row = f4 >> 6;
            int c   = (f4 & 63) * 4;
            cp_async16(&sm.k[0][row][c],
                       &g_qkv[(bL + 0 + row) * (3 * D_) + D_ + c]);
        }
        cp_commit();
    }

    const float* ep_base = edge_x + ((bL + q0 + qi) * L_ + kk) * E_;
    float4 evn[8];
#pragma unroll
    for (int c4 = 0; c4 < 8; c4++) evn[c4] = *(const float4*)&ep_base[c4 * 4];

    float acc[QT];
#pragma unroll
    for (int i = 0; i < QT; i++) acc[i] = 0.f;

    for (int i = 0; i < L_ / KT; i++) {
        const int k0 = i * KT;
        // prefetch next k tile into other buffer
        if (i + 1 < L_ / KT) {
            float* kb = &sm.k[(i + 1) & 1][0][0];
#pragma unroll
            for (int it = 0; it < 4; ++it) {
                int f4  = tid + it * 256;
                int row = f4 >> 6;
                int c   = (f4 & 63) * 4;
                cp_async16(kb + row * QSTR + c,
                           &g_qkv[(bL + k0 + KT + row) * (3 * D_) + D_ + c]);
            }
        }
        cp_commit();
        cp_wait1();           // tile i resident
        __syncthreads();      // also orders s/g reuse across iterations

        // v slice for this tile -> registers (phase-B mapping), issued early
        float v_reg[KT];
#pragma unroll
        for (int t = 0; t < KT; t++)
            v_reg[t] = g_qkv[(bL + k0 + t) * (3 * D_) + 2 * D_ + h * HD_ + lane];

        // current edge vector from prefetch; start prefetch of next
        float ev[E_];
#pragma unroll
        for (int c4 = 0; c4 < 8; c4++) {
            ev[c4 * 4 + 0] = evn[c4].x; ev[c4 * 4 + 1] = evn[c4].y;
            ev[c4 * 4 + 2] = evn[c4].z; ev[c4 * 4 + 3] = evn[c4].w;
        }
        if (i + 1 < L_ / KT) {
            const float* epn = ep_base + (size_t)(k0 + KT) * E_;
#pragma unroll
            for (int c4 = 0; c4 < 8; c4++) evn[c4] = *(const float4*)&epn[c4 * 4];
        }

        // ---- Phase A: per (qi,kk) pair ----
        {
            const float* kkrow = &sm.k[i & 1][kk][0];
            const float* qrow  = &sm.q[qi][0];
            float sh[H_];
#pragma unroll
            for (int hh = 0; hh < H_; ++hh) {
                float ea = sm.eb[hh];
                float ga = sm.gb[hh];
#pragma unroll
                for (int c4 = 0; c4 < 8; c4++) {
                    float4 we = *(const float4*)&sm.ew[hh][c4 * 4];
                    float4 wg = *(const float4*)&sm.gw[hh][c4 * 4];
                    ea += ev[c4*4+0]*we.x + ev[c4*4+1]*we.y + ev[c4*4+2]*we.z + ev[c4*4+3]*we.w;
                    ga += ev[c4*4+0]*wg.x + ev[c4*4+1]*wg.y + ev[c4*4+2]*wg.z + ev[c4*4+3]*wg.w;
                }
                float dot = 0.f;
#pragma unroll
                for (int c4 = 0; c4 < 8; c4++) {
                    float4 qv = *(const float4*)&qrow[hh * HD_ + c4 * 4];
                    float4 kv = *(const float4*)&kkrow[hh * HD_ + c4 * 4];
                    dot += qv.x*kv.x + qv.y*kv.y + qv.z*kv.z + qv.w*kv.w;
                }
                float sv = dot * SCALE_ + ea;
                sh[hh] = sv;
                sm.s[hh][qi][kk] = sv;
                sm.g[hh][qi][kk] = 1.0f / (1.0f + __expf(-ga));
            }
            // edge_out from RAW scores
            float* eo = edge_out + ((bL + q0 + qi) * L_ + k0 + kk) * E_;
#pragma unroll
            for (int c4 = 0; c4 < 8; c4++) {
                float vals[4];
#pragma unroll
                for (int u = 0; u < 4; u++) {
                    int c = c4 * 4 + u;
                    float4 w0 = *(const float4*)&sm.eow[c][0];
                    float4 w1 = *(const float4*)&sm.eow[c][4];
                    float a2 = sm.eob[c];
                    a2 += sh[0]*w0.x + sh[1]*w0.y + sh[2]*w0.z + sh[3]*w0.w;
                    a2 += sh[4]*w1.x + sh[5]*w1.y + sh[6]*w1.z + sh[7]*w1.w;
                    vals[u] = a2;
                }
                float4 o; o.x = vals[0]; o.y = vals[1]; o.z = vals[2]; o.w = vals[3];
                *(float4*)&eo[c4 * 4] = o;
            }
        }
        __syncthreads();

        // ---- Phase B: per-head online softmax + gated AV ----
        if (lane < QT) {
            const int q = lane;
            float mold = sm.m[h][q];
            float tmax = -1e30f;
#pragma unroll
            for (int t4 = 0; t4 < 4; t4++) {
                float4 sv = *(const float4*)&sm.s[h][q][t4 * 4];
                tmax = fmaxf(tmax, fmaxf(fmaxf(sv.x, sv.y), fmaxf(sv.z, sv.w)));
            }
            float mnew = fmaxf(mold, tmax);
            float r    = __expf(mold - mnew);
            float zs   = 0.f;
#pragma unroll
            for (int t4 = 0; t4 < 4; t4++) {
                float4 sv = *(const float4*)&sm.s[h][q][t4 * 4];
                float4 gv = *(const float4*)&sm.g[h][q][t4 * 4];
                float p0 = __expf(sv.x - mnew);
                float p1 = __expf(sv.y - mnew);
                float p2 = __expf(sv.z - mnew);
                float p3 = __expf(sv.w - mnew);
                zs += (p0 + p1) + (p2 + p3);           // Z ungated
                float4 o;
                o.x = p0 * gv.x; o.y = p1 * gv.y; o.z = p2 * gv.z; o.w = p3 * gv.w;
                *(float4*)&sm.s[h][q][t4 * 4] = o;     // numerator gated
            }
            sm.z[h][q] = sm.z[h][q] * r + zs;
            sm.m[h][q] = mnew;
            sm.r[h][q] = r;
        }
        __syncwarp();
#pragma unroll
        for (int q = 0; q < QT; q++) {
            float a = acc[q] * sm.r[h][q];
#pragma unroll
            for (int t4 = 0; t4 < 4; t4++) {
                float4 p = *(const float4*)&sm.s[h][q][t4 * 4];
                a += p.x * v_reg[t4*4+0] + p.y * v_reg[t4*4+1]
                   + p.z * v_reg[t4*4+2] + p.w * v_reg[t4*4+3];
            }
            acc[q] = a;
        }
        __syncthreads();
    }

    // --- epilogue ---
#pragma unroll
    for (int q = 0; q < QT; q++) {
        g_aout[(bL + q0 + q) * D_ + h * HD_ + lane] = acc[q] / sm.z[h][q];
    }
}

// ---------------------------------------------------------------------------
// kernel_launch
// ---------------------------------------------------------------------------
extern "C" void kernel_launch(void* const* d_in, const int* in_sizes, int n_in,
                              void* d_out, int out_size)
{
    const float* x       = (const float*)d_in[0];
    const float* edge_x  = (const float*)d_in[1];
    const float* in_w    = (const float*)d_in[2];
    const float* in_b    = (const float*)d_in[3];
    const float* out_w   = (const float*)d_in[4];
    const float* out_b   = (const float*)d_in[5];
    const float* e_w     = (const float*)d_in[6];
    const float* e_b     = (const float*)d_in[7];
    const float* g_w     = (const float*)d_in[8];
    const float* g_b     = (const float*)d_in[9];
    const float* eo_w    = (const float*)d_in[10];
    const float* eo_b    = (const float*)d_in[11];

    float* out0     = (float*)d_out;
    float* edge_out = out0 + (size_t)B_ * L_ * D_;

    float* qkv_ptr  = nullptr;
    float* aout_ptr = nullptr;
    cudaGetSymbolAddress((void**)&qkv_ptr,  g_qkv);
    cudaGetSymbolAddress((void**)&aout_ptr, g_aout);

    const int smem_bytes = (int)sizeof(AttnSmem);
    cudaFuncSetAttribute(edge_attn_kernel,
                         cudaFuncAttributeMaxDynamicSharedMemorySize, smem_bytes);

    sgemm_nt_bias<128, 128, 16><<<dim3(3 * D_ / 128, ROWS_ / 128), 256>>>(
        x, in_w, in_b, qkv_ptr, ROWS_, 3 * D_, D_);

    edge_attn_kernel<<<dim3(L_ / QT, B_), 256, smem_bytes>>>(
        edge_x, e_w, e_b, g_w, g_b, eo_w, eo_b, edge_out);

    sgemm_nt_bias<128, 128, 16><<<dim3(D_ / 128, ROWS_ / 128), 256>>>(
        aout_ptr, out_w, out_b, out0, ROWS_, D_, D_);
}

// round 3
// speedup vs baseline: 1.1362x; 1.1362x over previous
#include <cuda_runtime.h>
#include <math.h>

// ---------------------------------------------------------------------------
// Problem constants
// ---------------------------------------------------------------------------
constexpr int B_  = 32;
constexpr int L_  = 256;
constexpr int D_  = 256;
constexpr int E_  = 32;
constexpr int H_  = 8;
constexpr int HD_ = 32;
constexpr float SCALE_ = 0.17677669529663687f;  // 1/sqrt(32)

constexpr int ROWS_ = B_ * L_;   // 8192

// ---------------------------------------------------------------------------
// Device scratch
// ---------------------------------------------------------------------------
__device__ float g_qkv[ROWS_ * 3 * D_];   // [B*L, 768]  q|k|v
__device__ float g_aout[ROWS_ * D_];      // [B*L, 256]

// ---------------------------------------------------------------------------
// Kernel 1/3: C = A @ W^T + bias (unchanged, proven)
// ---------------------------------------------------------------------------
template<int BM, int BN, int BK>
__global__ __launch_bounds__(256)
void sgemm_nt_bias(const float* __restrict__ A, const float* __restrict__ W,
                   const float* __restrict__ bias, float* __restrict__ C,
                   int M, int N, int K)
{
    __shared__ float As[BK][BM + 4];
    __shared__ float Bs[BK][BN + 4];

    const int tid = threadIdx.x;
    const int tx  = tid & 15;
    const int ty  = tid >> 4;
    const int m0  = blockIdx.y * BM;
    const int n0  = blockIdx.x * BN;

    float acc[8][8];
#pragma unroll
    for (int i = 0; i < 8; i++)
#pragma unroll
        for (int j = 0; j < 8; j++) acc[i][j] = 0.f;

    for (int k0 = 0; k0 < K; k0 += BK) {
#pragma unroll
        for (int it = 0; it < (BM * BK) / (256 * 4); ++it) {
            int f4  = tid + it * 256;
            int row = f4 >> 2;
            int c4  = (f4 & 3) * 4;
            float4 v = *(const float4*)&A[(size_t)(m0 + row) * K + k0 + c4];
            As[c4 + 0][row] = v.x; As[c4 + 1][row] = v.y;
            As[c4 + 2][row] = v.z; As[c4 + 3][row] = v.w;
        }
#pragma unroll
        for (int it = 0; it < (BN * BK) / (256 * 4); ++it) {
            int f4  = tid + it * 256;
            int row = f4 >> 2;
            int c4  = (f4 & 3) * 4;
            float4 v = *(const float4*)&W[(size_t)(n0 + row) * K + k0 + c4];
            Bs[c4 + 0][row] = v.x; Bs[c4 + 1][row] = v.y;
            Bs[c4 + 2][row] = v.z; Bs[c4 + 3][row] = v.w;
        }
        __syncthreads();

#pragma unroll
        for (int kk = 0; kk < BK; ++kk) {
            float a[8], b[8];
            *(float4*)&a[0] = *(const float4*)&As[kk][ty * 8];
            *(float4*)&a[4] = *(const float4*)&As[kk][ty * 8 + 4];
            *(float4*)&b[0] = *(const float4*)&Bs[kk][tx * 8];
            *(float4*)&b[4] = *(const float4*)&Bs[kk][tx * 8 + 4];
#pragma unroll
            for (int i = 0; i < 8; i++)
#pragma unroll
                for (int j = 0; j < 8; j++)
                    acc[i][j] += a[i] * b[j];
        }
        __syncthreads();
    }

#pragma unroll
    for (int i = 0; i < 8; i++) {
        int m = m0 + ty * 8 + i;
#pragma unroll
        for (int j4 = 0; j4 < 2; j4++) {
            int n = n0 + tx * 8 + j4 * 4;
            float4 o;
            o.x = acc[i][j4 * 4 + 0] + bias[n + 0];
            o.y = acc[i][j4 * 4 + 1] + bias[n + 1];
            o.z = acc[i][j4 * 4 + 2] + bias[n + 2];
            o.w = acc[i][j4 * 4 + 3] + bias[n + 3];
            *(float4*)&C[(size_t)m * N + n] = o;
        }
    }
}

// ---------------------------------------------------------------------------
// Kernel 2: fused edge attention (v3 — coalesced smem-staged edge I/O)
// ---------------------------------------------------------------------------
constexpr int QT = 16;
constexpr int KT = 16;
constexpr int QSTR  = D_ + 4;    // 260
constexpr int SSTR  = KT + 4;    // 20
constexpr int EXSTR = 36;        // 36 ≡ 4 (mod 32): conflict-free 8-lane LDS.128 phases

struct AttnSmem {
    float q[QT][QSTR];           // 16.6 KB
    float k[KT][QSTR];           // 16.6 KB
    float ex[QT * KT][EXSTR];    // 36.9 KB edge staging (in AND out)
    float s[H_][QT][SSTR];       // 10.2 KB raw scores -> p*g
    float g[H_][QT][SSTR];       // 10.2 KB sigmoid gate
    float m[H_][QT];
    float z[H_][QT];
    float r[H_][QT];
    float ew[H_][E_];
    float gw[H_][E_];
    float eow[E_][H_];
    float eb[H_];
    float gb[H_];
    float eob[E_];
};

__global__ __launch_bounds__(256, 2)
void edge_attn_kernel(const float* __restrict__ edge_x,
                      const float* __restrict__ e_w, const float* __restrict__ e_b,
                      const float* __restrict__ g_w, const float* __restrict__ g_b,
                      const float* __restrict__ eo_w, const float* __restrict__ eo_b,
                      float* __restrict__ edge_out)
{
    extern __shared__ char smem_raw[];
    AttnSmem& sm = *reinterpret_cast<AttnSmem*>(smem_raw);

    const int tid = threadIdx.x;
    const int b   = blockIdx.y;
    const int q0  = blockIdx.x * QT;
    const size_t bL = (size_t)b * L_;

    // --- weights / state init ---
    ((float*)sm.ew)[tid]  = e_w[tid];
    ((float*)sm.gw)[tid]  = g_w[tid];
    ((float*)sm.eow)[tid] = eo_w[tid];
    if (tid < H_) { sm.eb[tid] = e_b[tid]; sm.gb[tid] = g_b[tid]; }
    if (tid < E_) { sm.eob[tid] = eo_b[tid]; }
    if (tid < H_ * QT) {
        ((float*)sm.m)[tid] = -1e30f;
        ((float*)sm.z)[tid] = 0.f;
    }

    // --- q tile (coalesced) ---
#pragma unroll
    for (int it = 0; it < 4; ++it) {
        int f4  = tid + it * 256;
        int row = f4 >> 6;
        int c   = (f4 & 63) * 4;
        *(float4*)&sm.q[row][c] =
            *(const float4*)&g_qkv[(bL + q0 + row) * (3 * D_) + c];
    }

    const int h    = tid >> 5;   // phase-B head
    const int lane = tid & 31;

    // coalesced edge staging mapping (per thread, 8 float4 covering 32KB tile)
    // f4 = it*256 + tid ; chunk(=qi) = f4>>7 ; within = f4&127
    // gmem: edge_x[((bL+q0+chunk)*L + k0)*E + within*4]
    // smem: ex[chunk*16 + (within>>3)][(within&7)*4]
    int ex_chunk[8], ex_within[8];
#pragma unroll
    for (int it = 0; it < 8; ++it) {
        int f4 = it * 256 + tid;
        ex_chunk[it]  = f4 >> 7;
        ex_within[it] = f4 & 127;
    }

    // --- prologue: prefetch edge tile 0 into registers (coalesced) ---
    float4 exr[8];
#pragma unroll
    for (int it = 0; it < 8; ++it)
        exr[it] = *(const float4*)&edge_x[((bL + q0 + ex_chunk[it]) * L_ + 0) * E_
                                          + ex_within[it] * 4];

    float acc[QT];
#pragma unroll
    for (int i = 0; i < QT; i++) acc[i] = 0.f;

    for (int i = 0; i < L_ / KT; i++) {
        const int k0 = i * KT;

        __syncthreads();   // ex / k buffers free for overwrite

        // stage edge tile i from prefetch registers (conflict-free STS.128)
#pragma unroll
        for (int it = 0; it < 8; ++it)
            *(float4*)&sm.ex[ex_chunk[it] * 16 + (ex_within[it] >> 3)]
                            [(ex_within[it] & 7) * 4] = exr[it];

        // stage k tile i (coalesced LDG -> STS)
#pragma unroll
        for (int it = 0; it < 4; ++it) {
            int f4  = tid + it * 256;
            int row = f4 >> 6;
            int c   = (f4 & 63) * 4;
            *(float4*)&sm.k[row][c] =
                *(const float4*)&g_qkv[(bL + k0 + row) * (3 * D_) + D_ + c];
        }

        // prefetch edge tile i+1 (coalesced)
        if (i + 1 < L_ / KT) {
#pragma unroll
            for (int it = 0; it < 8; ++it)
                exr[it] = *(const float4*)
                    &edge_x[((bL + q0 + ex_chunk[it]) * L_ + k0 + KT) * E_
                            + ex_within[it] * 4];
        }

        // v slice for this tile -> registers (coalesced per (h,t))
        float v_reg[KT];
#pragma unroll
        for (int t = 0; t < KT; t++)
            v_reg[t] = g_qkv[(bL + k0 + t) * (3 * D_) + 2 * D_ + h * HD_ + lane];

        __syncthreads();   // ex + k visible

        // ---- Phase A: thread owns pair (qi = tid>>4, kk = tid&15) = ex[tid] ----
        {
            const int qi = tid >> 4;
            const int kk = tid & 15;
            float ev[E_];
#pragma unroll
            for (int c4 = 0; c4 < 8; c4++) {
                float4 t4 = *(const float4*)&sm.ex[tid][c4 * 4];
                ev[c4*4+0] = t4.x; ev[c4*4+1] = t4.y;
                ev[c4*4+2] = t4.z; ev[c4*4+3] = t4.w;
            }
            const float* kkrow = &sm.k[kk][0];
            const float* qrow  = &sm.q[qi][0];
            float sh[H_];
#pragma unroll
            for (int hh = 0; hh < H_; ++hh) {
                float ea = sm.eb[hh];
                float ga = sm.gb[hh];
#pragma unroll
                for (int c4 = 0; c4 < 8; c4++) {
                    float4 we = *(const float4*)&sm.ew[hh][c4 * 4];
                    float4 wg = *(const float4*)&sm.gw[hh][c4 * 4];
                    ea += ev[c4*4+0]*we.x + ev[c4*4+1]*we.y + ev[c4*4+2]*we.z + ev[c4*4+3]*we.w;
                    ga += ev[c4*4+0]*wg.x + ev[c4*4+1]*wg.y + ev[c4*4+2]*wg.z + ev[c4*4+3]*wg.w;
                }
                float dot = 0.f;
#pragma unroll
                for (int c4 = 0; c4 < 8; c4++) {
                    float4 qv = *(const float4*)&qrow[hh * HD_ + c4 * 4];
                    float4 kv = *(const float4*)&kkrow[hh * HD_ + c4 * 4];
                    dot += qv.x*kv.x + qv.y*kv.y + qv.z*kv.z + qv.w*kv.w;
                }
                float sv = dot * SCALE_ + ea;
                sh[hh] = sv;
                sm.s[hh][qi][kk] = sv;
                sm.g[hh][qi][kk] = 1.0f / (1.0f + __expf(-ga));
            }
            // edge_out values from RAW scores -> back into own ex row
#pragma unroll
            for (int c4 = 0; c4 < 8; c4++) {
                float vals[4];
#pragma unroll
                for (int u = 0; u < 4; u++) {
                    int c = c4 * 4 + u;
                    float4 w0 = *(const float4*)&sm.eow[c][0];
                    float4 w1 = *(const float4*)&sm.eow[c][4];
                    float a2 = sm.eob[c];
                    a2 += sh[0]*w0.x + sh[1]*w0.y + sh[2]*w0.z + sh[3]*w0.w;
                    a2 += sh[4]*w1.x + sh[5]*w1.y + sh[6]*w1.z + sh[7]*w1.w;
                    vals[u] = a2;
                }
                float4 o; o.x = vals[0]; o.y = vals[1]; o.z = vals[2]; o.w = vals[3];
                *(float4*)&sm.ex[tid][c4 * 4] = o;
            }
        }
        __syncthreads();   // ex now holds edge_out tile; s/g complete

        // coalesced edge_out store (LDS conflict-free, STG coalesced)
#pragma unroll
        for (int it = 0; it < 8; ++it) {
            float4 v4 = *(const float4*)&sm.ex[ex_chunk[it] * 16 + (ex_within[it] >> 3)]
                                              [(ex_within[it] & 7) * 4];
            *(float4*)&edge_out[((bL + q0 + ex_chunk[it]) * L_ + k0) * E_
                                + ex_within[it] * 4] = v4;
        }

        // ---- Phase B: per-head online softmax + gated AV ----
        if (lane < QT) {
            const int q = lane;
            float mold = sm.m[h][q];
            float tmax = -1e30f;
#pragma unroll
            for (int t4 = 0; t4 < 4; t4++) {
                float4 sv = *(const float4*)&sm.s[h][q][t4 * 4];
                tmax = fmaxf(tmax, fmaxf(fmaxf(sv.x, sv.y), fmaxf(sv.z, sv.w)));
            }
            float mnew = fmaxf(mold, tmax);
            float r    = __expf(mold - mnew);
            float zs   = 0.f;
#pragma unroll
            for (int t4 = 0; t4 < 4; t4++) {
                float4 sv = *(const float4*)&sm.s[h][q][t4 * 4];
                float4 gv = *(const float4*)&sm.g[h][q][t4 * 4];
                float p0 = __expf(sv.x - mnew);
                float p1 = __expf(sv.y - mnew);
                float p2 = __expf(sv.z - mnew);
                float p3 = __expf(sv.w - mnew);
                zs += (p0 + p1) + (p2 + p3);           // Z ungated
                float4 o;
                o.x = p0 * gv.x; o.y = p1 * gv.y; o.z = p2 * gv.z; o.w = p3 * gv.w;
                *(float4*)&sm.s[h][q][t4 * 4] = o;     // numerator gated
            }
            sm.z[h][q] = sm.z[h][q] * r + zs;
            sm.m[h][q] = mnew;
            sm.r[h][q] = r;
        }
        __syncwarp();
#pragma unroll
        for (int q = 0; q < QT; q++) {
            float a = acc[q] * sm.r[h][q];
#pragma unroll
            for (int t4 = 0; t4 < 4; t4++) {
                float4 p = *(const float4*)&sm.s[h][q][t4 * 4];
                a += p.x * v_reg[t4*4+0] + p.y * v_reg[t4*4+1]
                   + p.z * v_reg[t4*4+2] + p.w * v_reg[t4*4+3];
            }
            acc[q] = a;
        }
    }

    // --- epilogue ---
#pragma unroll
    for (int q = 0; q < QT; q++) {
        g_aout[(bL + q0 + q) * D_ + h * HD_ + lane] = acc[q] / sm.z[h][q];
    }
}

// ---------------------------------------------------------------------------
// kernel_launch
// ---------------------------------------------------------------------------
extern "C" void kernel_launch(void* const* d_in, const int* in_sizes, int n_in,
                              void* d_out, int out_size)
{
    const float* x       = (const float*)d_in[0];
    const float* edge_x  = (const float*)d_in[1];
    const float* in_w    = (const float*)d_in[2];
    const float* in_b    = (const float*)d_in[3];
    const float* out_w   = (const float*)d_in[4];
    const float* out_b   = (const float*)d_in[5];
    const float* e_w     = (const float*)d_in[6];
    const float* e_b     = (const float*)d_in[7];
    const float* g_w     = (const float*)d_in[8];
    const float* g_b     = (const float*)d_in[9];
    const float* eo_w    = (const float*)d_in[10];
    const float* eo_b    = (const float*)d_in[11];

    float* out0     = (float*)d_out;
    float* edge_out = out0 + (size_t)B_ * L_ * D_;

    float* qkv_ptr  = nullptr;
    float* aout_ptr = nullptr;
    cudaGetSymbolAddress((void**)&qkv_ptr,  g_qkv);
    cudaGetSymbolAddress((void**)&aout_ptr, g_aout);

    const int smem_bytes = (int)sizeof(AttnSmem);
    cudaFuncSetAttribute(edge_attn_kernel,
                         cudaFuncAttributeMaxDynamicSharedMemorySize, smem_bytes);

    sgemm_nt_bias<128, 128, 16><<<dim3(3 * D_ / 128, ROWS_ / 128), 256>>>(
        x, in_w, in_b, qkv_ptr, ROWS_, 3 * D_, D_);

    edge_attn_kernel<<<dim3(L_ / QT, B_), 256, smem_bytes>>>(
        edge_x, e_w, e_b, g_w, g_b, eo_w, eo_b, edge_out);

    sgemm_nt_bias<128, 128, 16><<<dim3(D_ / 128, ROWS_ / 128), 256>>>(
        aout_ptr, out_w, out_b, out0, ROWS_, D_, D_);
}

// round 4
// speedup vs baseline: 1.1597x; 1.0207x over previous
#include <cuda_runtime.h>
#include <math.h>

// ---------------------------------------------------------------------------
// Problem constants
// ---------------------------------------------------------------------------
constexpr int B_  = 32;
constexpr int L_  = 256;
constexpr int D_  = 256;
constexpr int E_  = 32;
constexpr int H_  = 8;
constexpr int HD_ = 32;
constexpr float SCALE_ = 0.17677669529663687f;  // 1/sqrt(32)

constexpr int ROWS_ = B_ * L_;   // 8192

// ---------------------------------------------------------------------------
// Device scratch
// ---------------------------------------------------------------------------
__device__ float g_qkv[ROWS_ * 3 * D_];   // [B*L, 768]  q|k|v
__device__ float g_aout[ROWS_ * D_];      // [B*L, 256]

// ---------------------------------------------------------------------------
// packed f32x2 helpers (sm_103a)
// ---------------------------------------------------------------------------
using u64 = unsigned long long;

__device__ __forceinline__ unsigned s2u(const void* p) {
    return (unsigned)__cvta_generic_to_shared(p);
}
__device__ __forceinline__ void lds_v2(u64& a, u64& b, unsigned addr) {
    asm volatile("ld.shared.v2.b64 {%0,%1}, [%2];" : "=l"(a), "=l"(b) : "r"(addr));
}
__device__ __forceinline__ u64 lds_1(unsigned addr) {
    u64 a; asm volatile("ld.shared.b64 %0, [%1];" : "=l"(a) : "r"(addr)); return a;
}
__device__ __forceinline__ void sts_1(unsigned addr, u64 v) {
    asm volatile("st.shared.b64 [%0], %1;" :: "r"(addr), "l"(v));
}
__device__ __forceinline__ u64 fma2(u64 a, u64 b, u64 c) {
    u64 d; asm("fma.rn.f32x2 %0, %1, %2, %3;" : "=l"(d) : "l"(a), "l"(b), "l"(c));
    return d;
}
__device__ __forceinline__ u64 mul2(u64 a, u64 b) {
    u64 d; asm("mul.rn.f32x2 %0, %1, %2;" : "=l"(d) : "l"(a), "l"(b));
    return d;
}
__device__ __forceinline__ float hsum2(u64 a) {
    float lo, hi;
    asm("mov.b64 {%0,%1}, %2;" : "=f"(lo), "=f"(hi) : "l"(a));
    return lo + hi;
}
__device__ __forceinline__ u64 dup2(float x) {
    u64 d; asm("mov.b64 %0, {%1,%1};" : "=l"(d) : "f"(x)); return d;
}
__device__ __forceinline__ u64 pk2(float x, float y) {
    u64 d; asm("mov.b64 %0, {%1,%2};" : "=l"(d) : "f"(x), "f"(y)); return d;
}

// ---------------------------------------------------------------------------
// Kernel 1/3: C = A @ W^T + bias (unchanged, proven)
// ---------------------------------------------------------------------------
template<int BM, int BN, int BK>
__global__ __launch_bounds__(256)
void sgemm_nt_bias(const float* __restrict__ A, const float* __restrict__ W,
                   const float* __restrict__ bias, float* __restrict__ C,
                   int M, int N, int K)
{
    __shared__ float As[BK][BM + 4];
    __shared__ float Bs[BK][BN + 4];

    const int tid = threadIdx.x;
    const int tx  = tid & 15;
    const int ty  = tid >> 4;
    const int m0  = blockIdx.y * BM;
    const int n0  = blockIdx.x * BN;

    float acc[8][8];
#pragma unroll
    for (int i = 0; i < 8; i++)
#pragma unroll
        for (int j = 0; j < 8; j++) acc[i][j] = 0.f;

    for (int k0 = 0; k0 < K; k0 += BK) {
#pragma unroll
        for (int it = 0; it < (BM * BK) / (256 * 4); ++it) {
            int f4  = tid + it * 256;
            int row = f4 >> 2;
            int c4  = (f4 & 3) * 4;
            float4 v = *(const float4*)&A[(size_t)(m0 + row) * K + k0 + c4];
            As[c4 + 0][row] = v.x; As[c4 + 1][row] = v.y;
            As[c4 + 2][row] = v.z; As[c4 + 3][row] = v.w;
        }
#pragma unroll
        for (int it = 0; it < (BN * BK) / (256 * 4); ++it) {
            int f4  = tid + it * 256;
            int row = f4 >> 2;
            int c4  = (f4 & 3) * 4;
            float4 v = *(const float4*)&W[(size_t)(n0 + row) * K + k0 + c4];
            Bs[c4 + 0][row] = v.x; Bs[c4 + 1][row] = v.y;
            Bs[c4 + 2][row] = v.z; Bs[c4 + 3][row] = v.w;
        }
        __syncthreads();

#pragma unroll
        for (int kk = 0; kk < BK; ++kk) {
            float a[8], b[8];
            *(float4*)&a[0] = *(const float4*)&As[kk][ty * 8];
            *(float4*)&a[4] = *(const float4*)&As[kk][ty * 8 + 4];
            *(float4*)&b[0] = *(const float4*)&Bs[kk][tx * 8];
            *(float4*)&b[4] = *(const float4*)&Bs[kk][tx * 8 + 4];
#pragma unroll
            for (int i = 0; i < 8; i++)
#pragma unroll
                for (int j = 0; j < 8; j++)
                    acc[i][j] += a[i] * b[j];
        }
        __syncthreads();
    }

#pragma unroll
    for (int i = 0; i < 8; i++) {
        int m = m0 + ty * 8 + i;
#pragma unroll
        for (int j4 = 0; j4 < 2; j4++) {
            int n = n0 + tx * 8 + j4 * 4;
            float4 o;
            o.x = acc[i][j4 * 4 + 0] + bias[n + 0];
            o.y = acc[i][j4 * 4 + 1] + bias[n + 1];
            o.z = acc[i][j4 * 4 + 2] + bias[n + 2];
            o.w = acc[i][j4 * 4 + 3] + bias[n + 3];
            *(float4*)&C[(size_t)m * N + n] = o;
        }
    }
}

// ---------------------------------------------------------------------------
// Kernel 2: fused edge attention (v4 — packed f32x2 math)
// ---------------------------------------------------------------------------
constexpr int QT = 16;
constexpr int KT = 16;
constexpr int QSTR  = D_ + 4;    // 260 floats = 1040 B (16B-aligned)
constexpr int SSTR  = KT + 4;    // 20 floats = 80 B   (16B-aligned)
constexpr int EXSTR = 36;        // 36 floats = 144 B  (16B-aligned, conflict-free)

struct AttnSmem {
    float q[QT][QSTR];
    float k[KT][QSTR];
    float ex[QT * KT][EXSTR];    // edge staging (in AND out)
    float s[H_][QT][SSTR];       // raw scores -> p*g
    float g[H_][QT][SSTR];       // sigmoid gate
    float m[H_][QT];
    float z[H_][QT];
    float r[H_][QT];
    float ew[H_][E_];            // e_w rows (128B each)
    float gw[H_][E_];
    float eowp[16][H_][2];       // paired eo_w: eowp[c2][h] = (eo_w[2c2][h], eo_w[2c2+1][h])
    float eb[H_];
    float gb[H_];
    float eob[E_];
};

__global__ __launch_bounds__(256, 2)
void edge_attn_kernel(const float* __restrict__ edge_x,
                      const float* __restrict__ e_w, const float* __restrict__ e_b,
                      const float* __restrict__ g_w, const float* __restrict__ g_b,
                      const float* __restrict__ eo_w, const float* __restrict__ eo_b,
                      float* __restrict__ edge_out)
{
    extern __shared__ char smem_raw[];
    AttnSmem& sm = *reinterpret_cast<AttnSmem*>(smem_raw);

    const int tid = threadIdx.x;
    const int b   = blockIdx.y;
    const int q0  = blockIdx.x * QT;
    const size_t bL = (size_t)b * L_;

    // --- weights / state init ---
    ((float*)sm.ew)[tid]  = e_w[tid];
    ((float*)sm.gw)[tid]  = g_w[tid];
    if (tid < 128) {   // eowp[c2][hh] = (eo_w[2c2][hh], eo_w[2c2+1][hh])
        int c2 = tid >> 3, hh = tid & 7;
        sm.eowp[c2][hh][0] = eo_w[(2 * c2 + 0) * H_ + hh];
        sm.eowp[c2][hh][1] = eo_w[(2 * c2 + 1) * H_ + hh];
    }
    if (tid < H_) { sm.eb[tid] = e_b[tid]; sm.gb[tid] = g_b[tid]; }
    if (tid < E_) { sm.eob[tid] = eo_b[tid]; }
    if (tid < H_ * QT) {
        ((float*)sm.m)[tid] = -1e30f;
        ((float*)sm.z)[tid] = 0.f;
    }

    // --- q tile (coalesced) ---
#pragma unroll
    for (int it = 0; it < 4; ++it) {
        int f4  = tid + it * 256;
        int row = f4 >> 6;
        int c   = (f4 & 63) * 4;
        *(float4*)&sm.q[row][c] =
            *(const float4*)&g_qkv[(bL + q0 + row) * (3 * D_) + c];
    }

    const int h    = tid >> 5;   // phase-B head
    const int lane = tid & 31;
    const int qi   = tid >> 4;   // phase-A query
    const int kk   = tid & 15;   // phase-A key

    // smem base addresses (u32 shared-window)
    const unsigned exrow_a = s2u(&sm.ex[tid][0]);
    const unsigned q_a     = s2u(&sm.q[qi][0]);
    const unsigned k_a     = s2u(&sm.k[kk][0]);
    const unsigned ew_a    = s2u(&sm.ew[0][0]);
    const unsigned gw_a    = s2u(&sm.gw[0][0]);
    const unsigned eowp_a  = s2u(&sm.eowp[0][0][0]);
    const unsigned eob_a   = s2u(&sm.eob[0]);
    const unsigned srow_a  = s2u(&sm.s[h][0][0]);   // + q*80
    const unsigned grow_a  = s2u(&sm.g[h][0][0]);

    // coalesced edge staging mapping
    int ex_chunk[8], ex_within[8];
#pragma unroll
    for (int it = 0; it < 8; ++it) {
        int f4 = it * 256 + tid;
        ex_chunk[it]  = f4 >> 7;
        ex_within[it] = f4 & 127;
    }

    // --- prologue: prefetch edge tile 0 (coalesced) ---
    float4 exr[8];
#pragma unroll
    for (int it = 0; it < 8; ++it)
        exr[it] = *(const float4*)&edge_x[((bL + q0 + ex_chunk[it]) * L_ + 0) * E_
                                          + ex_within[it] * 4];

    u64 acc2[QT];
#pragma unroll
    for (int i = 0; i < QT; i++) acc2[i] = 0ull;

    for (int i = 0; i < L_ / KT; i++) {
        const int k0 = i * KT;

        __syncthreads();   // ex / k buffers free for overwrite

        // stage edge tile i (conflict-free STS.128)
#pragma unroll
        for (int it = 0; it < 8; ++it)
            *(float4*)&sm.ex[ex_chunk[it] * 16 + (ex_within[it] >> 3)]
                            [(ex_within[it] & 7) * 4] = exr[it];

        // stage k tile i
#pragma unroll
        for (int it = 0; it < 4; ++it) {
            int f4  = tid + it * 256;
            int row = f4 >> 6;
            int c   = (f4 & 63) * 4;
            *(float4*)&sm.k[row][c] =
                *(const float4*)&g_qkv[(bL + k0 + row) * (3 * D_) + D_ + c];
        }

        // prefetch edge tile i+1
        if (i + 1 < L_ / KT) {
#pragma unroll
            for (int it = 0; it < 8; ++it)
                exr[it] = *(const float4*)
                    &edge_x[((bL + q0 + ex_chunk[it]) * L_ + k0 + KT) * E_
                            + ex_within[it] * 4];
        }

        // v slice -> packed registers (coalesced per (h,t))
        u64 v2[KT / 2];
#pragma unroll
        for (int t2 = 0; t2 < KT / 2; t2++) {
            float a = g_qkv[(bL + k0 + 2 * t2 + 0) * (3 * D_) + 2 * D_ + h * HD_ + lane];
            float c = g_qkv[(bL + k0 + 2 * t2 + 1) * (3 * D_) + 2 * D_ + h * HD_ + lane];
            v2[t2] = pk2(a, c);
        }

        __syncthreads();   // ex + k visible

        // ---- Phase A (f32x2): thread owns pair (qi, kk) ----
        {
            // edge vector as 16 channel-pairs
            u64 ev2[16];
#pragma unroll
            for (int j = 0; j < 8; ++j)
                lds_v2(ev2[2 * j], ev2[2 * j + 1], exrow_a + j * 16);

            float sh[H_];
#pragma unroll
            for (int hh = 0; hh < H_; ++hh) {
                u64 ea2 = 0ull, ga2 = 0ull, dot2 = 0ull;
                const unsigned ewr = ew_a + hh * 128;
                const unsigned gwr = gw_a + hh * 128;
                const unsigned qr  = q_a + hh * 128;
                const unsigned kr  = k_a + hh * 128;
#pragma unroll
                for (int j = 0; j < 8; ++j) {
                    u64 w0, w1;
                    lds_v2(w0, w1, ewr + j * 16);
                    ea2 = fma2(ev2[2 * j], w0, ea2);
                    ea2 = fma2(ev2[2 * j + 1], w1, ea2);
                    lds_v2(w0, w1, gwr + j * 16);
                    ga2 = fma2(ev2[2 * j], w0, ga2);
                    ga2 = fma2(ev2[2 * j + 1], w1, ga2);
                    u64 qa, qb, ka, kb;
                    lds_v2(qa, qb, qr + j * 16);
                    lds_v2(ka, kb, kr + j * 16);
                    dot2 = fma2(qa, ka, dot2);
                    dot2 = fma2(qb, kb, dot2);
                }
                float ea = hsum2(ea2) + sm.eb[hh];
                float ga = hsum2(ga2) + sm.gb[hh];
                float sv = hsum2(dot2) * SCALE_ + ea;
                sh[hh] = sv;
                sm.s[hh][qi][kk] = sv;
                sm.g[hh][qi][kk] = 1.0f / (1.0f + __expf(-ga));
            }

            // edge_out from RAW scores (paired outputs) -> back into ex row
            u64 shd[H_];
#pragma unroll
            for (int hh = 0; hh < H_; ++hh) shd[hh] = dup2(sh[hh]);
#pragma unroll
            for (int c2 = 0; c2 < 16; ++c2) {
                u64 a2 = lds_1(eob_a + c2 * 8);
                const unsigned wr = eowp_a + c2 * 64;
#pragma unroll
                for (int j = 0; j < 4; ++j) {
                    u64 w0, w1;
                    lds_v2(w0, w1, wr + j * 16);
                    a2 = fma2(shd[2 * j], w0, a2);
                    a2 = fma2(shd[2 * j + 1], w1, a2);
                }
                sts_1(exrow_a + c2 * 8, a2);
            }
        }
        __syncthreads();   // ex holds edge_out tile; s/g complete

        // coalesced edge_out store
#pragma unroll
        for (int it = 0; it < 8; ++it) {
            float4 v4 = *(const float4*)&sm.ex[ex_chunk[it] * 16 + (ex_within[it] >> 3)]
                                              [(ex_within[it] & 7) * 4];
            *(float4*)&edge_out[((bL + q0 + ex_chunk[it]) * L_ + k0) * E_
                                + ex_within[it] * 4] = v4;
        }

        // ---- Phase B: per-head online softmax + gated AV (f32x2) ----
        if (lane < QT) {
            const int q = lane;
            float mold = sm.m[h][q];
            float tmax = -1e30f;
#pragma unroll
            for (int t4 = 0; t4 < 4; t4++) {
                float4 sv = *(const float4*)&sm.s[h][q][t4 * 4];
                tmax = fmaxf(tmax, fmaxf(fmaxf(sv.x, sv.y), fmaxf(sv.z, sv.w)));
            }
            float mnew = fmaxf(mold, tmax);
            float r    = __expf(mold - mnew);
            float zs   = 0.f;
#pragma unroll
            for (int t4 = 0; t4 < 4; t4++) {
                float4 sv = *(const float4*)&sm.s[h][q][t4 * 4];
                float4 gv = *(const float4*)&sm.g[h][q][t4 * 4];
                float p0 = __expf(sv.x - mnew);
                float p1 = __expf(sv.y - mnew);
                float p2 = __expf(sv.z - mnew);
                float p3 = __expf(sv.w - mnew);
                zs += (p0 + p1) + (p2 + p3);           // Z ungated
                float4 o;
                o.x = p0 * gv.x; o.y = p1 * gv.y; o.z = p2 * gv.z; o.w = p3 * gv.w;
                *(float4*)&sm.s[h][q][t4 * 4] = o;     // numerator gated
            }
            sm.z[h][q] = sm.z[h][q] * r + zs;
            sm.m[h][q] = mnew;
            sm.r[h][q] = r;
        }
        __syncwarp();
#pragma unroll
        for (int q = 0; q < QT; q++) {
            u64 a2 = mul2(acc2[q], dup2(sm.r[h][q]));
            const unsigned sr = srow_a + q * (SSTR * 4);
#pragma unroll
            for (int j = 0; j < 4; ++j) {
                u64 p0, p1;
                lds_v2(p0, p1, sr + j * 16);
                a2 = fma2(p0, v2[2 * j], a2);
                a2 = fma2(p1, v2[2 * j + 1], a2);
            }
            acc2[q] = a2;
        }
    }

    // --- epilogue ---
#pragma unroll
    for (int q = 0; q < QT; q++) {
        g_aout[(bL + q0 + q) * D_ + h * HD_ + lane] = hsum2(acc2[q]) / sm.z[h][q];
    }
    (void)grow_a;
}

// ---------------------------------------------------------------------------
// kernel_launch
// ---------------------------------------------------------------------------
extern "C" void kernel_launch(void* const* d_in, const int* in_sizes, int n_in,
                              void* d_out, int out_size)
{
    const float* x       = (const float*)d_in[0];
    const float* edge_x  = (const float*)d_in[1];
    const float* in_w    = (const float*)d_in[2];
    const float* in_b    = (const float*)d_in[3];
    const float* out_w   = (const float*)d_in[4];
    const float* out_b   = (const float*)d_in[5];
    const float* e_w     = (const float*)d_in[6];
    const float* e_b     = (const float*)d_in[7];
    const float* g_w     = (const float*)d_in[8];
    const float* g_b     = (const float*)d_in[9];
    const float* eo_w    = (const float*)d_in[10];
    const float* eo_b    = (const float*)d_in[11];

    float* out0     = (float*)d_out;
    float* edge_out = out0 + (size_t)B_ * L_ * D_;

    float* qkv_ptr  = nullptr;
    float* aout_ptr = nullptr;
    cudaGetSymbolAddress((void**)&qkv_ptr,  g_qkv);
    cudaGetSymbolAddress((void**)&aout_ptr, g_aout);

    const int smem_bytes = (int)sizeof(AttnSmem);
    cudaFuncSetAttribute(edge_attn_kernel,
                         cudaFuncAttributeMaxDynamicSharedMemorySize, smem_bytes);

    sgemm_nt_bias<128, 128, 16><<<dim3(3 * D_ / 128, ROWS_ / 128), 256>>>(
        x, in_w, in_b, qkv_ptr, ROWS_, 3 * D_, D_);

    edge_attn_kernel<<<dim3(L_ / QT, B_), 256, smem_bytes>>>(
        edge_x, e_w, e_b, g_w, g_b, eo_w, eo_b, edge_out);

    sgemm_nt_bias<128, 128, 16><<<dim3(D_ / 128, ROWS_ / 128), 256>>>(
        aout_ptr, out_w, out_b, out0, ROWS_, D_, D_);
}

// round 5
// speedup vs baseline: 1.2620x; 1.0882x over previous
#include <cuda_runtime.h>
#include <math.h>

// ---------------------------------------------------------------------------
// Problem constants
// ---------------------------------------------------------------------------
constexpr int B_  = 32;
constexpr int L_  = 256;
constexpr int D_  = 256;
constexpr int E_  = 32;
constexpr int H_  = 8;
constexpr int HD_ = 32;
constexpr float SCALE_ = 0.17677669529663687f;  // 1/sqrt(32)

constexpr int ROWS_ = B_ * L_;   // 8192

// ---------------------------------------------------------------------------
// Device scratch
// ---------------------------------------------------------------------------
__device__ float g_qkv[ROWS_ * 3 * D_];   // [B*L, 768]  q|k|v
__device__ float g_aout[ROWS_ * D_];      // [B*L, 256]

// ---------------------------------------------------------------------------
// packed f32x2 + cp.async helpers (sm_103a)
// ---------------------------------------------------------------------------
using u64 = unsigned long long;

__device__ __forceinline__ unsigned s2u(const void* p) {
    return (unsigned)__cvta_generic_to_shared(p);
}
__device__ __forceinline__ void lds_v2(u64& a, u64& b, unsigned addr) {
    asm volatile("ld.shared.v2.b64 {%0,%1}, [%2];" : "=l"(a), "=l"(b) : "r"(addr));
}
__device__ __forceinline__ u64 lds_1(unsigned addr) {
    u64 a; asm volatile("ld.shared.b64 %0, [%1];" : "=l"(a) : "r"(addr)); return a;
}
__device__ __forceinline__ void sts_1(unsigned addr, u64 v) {
    asm volatile("st.shared.b64 [%0], %1;" :: "r"(addr), "l"(v));
}
__device__ __forceinline__ u64 fma2(u64 a, u64 b, u64 c) {
    u64 d; asm("fma.rn.f32x2 %0, %1, %2, %3;" : "=l"(d) : "l"(a), "l"(b), "l"(c));
    return d;
}
__device__ __forceinline__ u64 mul2(u64 a, u64 b) {
    u64 d; asm("mul.rn.f32x2 %0, %1, %2;" : "=l"(d) : "l"(a), "l"(b));
    return d;
}
__device__ __forceinline__ float hsum2(u64 a) {
    float lo, hi;
    asm("mov.b64 {%0,%1}, %2;" : "=f"(lo), "=f"(hi) : "l"(a));
    return lo + hi;
}
__device__ __forceinline__ void unpk2(u64 a, float& lo, float& hi) {
    asm("mov.b64 {%0,%1}, %2;" : "=f"(lo), "=f"(hi) : "l"(a));
}
__device__ __forceinline__ u64 dup2(float x) {
    u64 d; asm("mov.b64 %0, {%1,%1};" : "=l"(d) : "f"(x)); return d;
}
__device__ __forceinline__ u64 pk2(float x, float y) {
    u64 d; asm("mov.b64 %0, {%1,%2};" : "=l"(d) : "f"(x), "f"(y)); return d;
}
__device__ __forceinline__ void cp_async16(unsigned smem_dst, const void* gmem_src) {
    asm volatile("cp.async.cg.shared.global [%0], [%1], 16;\n"
                 :: "r"(smem_dst), "l"(gmem_src) : "memory");
}
__device__ __forceinline__ void cp_commit() {
    asm volatile("cp.async.commit_group;\n" ::: "memory");
}
__device__ __forceinline__ void cp_wait0() {
    asm volatile("cp.async.wait_group 0;\n" ::: "memory");
}

// ---------------------------------------------------------------------------
// Kernel 1/3: C = A @ W^T + bias (f32x2 inner loop)
// ---------------------------------------------------------------------------
template<int BM, int BN, int BK>
__global__ __launch_bounds__(256)
void sgemm_nt_bias(const float* __restrict__ A, const float* __restrict__ W,
                   const float* __restrict__ bias, float* __restrict__ C,
                   int M, int N, int K)
{
    __shared__ float As[BK][BM + 4];
    __shared__ float Bs[BK][BN + 4];

    const int tid = threadIdx.x;
    const int tx  = tid & 15;
    const int ty  = tid >> 4;
    const int m0  = blockIdx.y * BM;
    const int n0  = blockIdx.x * BN;

    u64 acc2[8][4];
#pragma unroll
    for (int i = 0; i < 8; i++)
#pragma unroll
        for (int j = 0; j < 4; j++) acc2[i][j] = 0ull;

    for (int k0 = 0; k0 < K; k0 += BK) {
#pragma unroll
        for (int it = 0; it < (BM * BK) / (256 * 4); ++it) {
            int f4  = tid + it * 256;
            int row = f4 >> 2;
            int c4  = (f4 & 3) * 4;
            float4 v = *(const float4*)&A[(size_t)(m0 + row) * K + k0 + c4];
            As[c4 + 0][row] = v.x; As[c4 + 1][row] = v.y;
            As[c4 + 2][row] = v.z; As[c4 + 3][row] = v.w;
        }
#pragma unroll
        for (int it = 0; it < (BN * BK) / (256 * 4); ++it) {
            int f4  = tid + it * 256;
            int row = f4 >> 2;
            int c4  = (f4 & 3) * 4;
            float4 v = *(const float4*)&W[(size_t)(n0 + row) * K + k0 + c4];
            Bs[c4 + 0][row] = v.x; Bs[c4 + 1][row] = v.y;
            Bs[c4 + 2][row] = v.z; Bs[c4 + 3][row] = v.w;
        }
        __syncthreads();

#pragma unroll
        for (int kk = 0; kk < BK; ++kk) {
            float a[8];
            *(float4*)&a[0] = *(const float4*)&As[kk][ty * 8];
            *(float4*)&a[4] = *(const float4*)&As[kk][ty * 8 + 4];
            u64 b2[4];
            const u64* bp = (const u64*)&Bs[kk][tx * 8];
            b2[0] = bp[0]; b2[1] = bp[1]; b2[2] = bp[2]; b2[3] = bp[3];
            u64 ad[8];
#pragma unroll
            for (int i = 0; i < 8; i++) ad[i] = dup2(a[i]);
#pragma unroll
            for (int i = 0; i < 8; i++)
#pragma unroll
                for (int j = 0; j < 4; j++)
                    acc2[i][j] = fma2(ad[i], b2[j], acc2[i][j]);
        }
        __syncthreads();
    }

#pragma unroll
    for (int i = 0; i < 8; i++) {
        int m = m0 + ty * 8 + i;
#pragma unroll
        for (int j4 = 0; j4 < 2; j4++) {
            int n = n0 + tx * 8 + j4 * 4;
            float l0, h0, l1, h1;
            unpk2(acc2[i][j4 * 2 + 0], l0, h0);
            unpk2(acc2[i][j4 * 2 + 1], l1, h1);
            float4 o;
            o.x = l0 + bias[n + 0];
            o.y = h0 + bias[n + 1];
            o.z = l1 + bias[n + 2];
            o.w = h1 + bias[n + 3];
            *(float4*)&C[(size_t)m * N + n] = o;
        }
    }
}

// ---------------------------------------------------------------------------
// Kernel 2: fused edge attention (v5 — cp.async, no spills, swizzled ex)
// ---------------------------------------------------------------------------
constexpr int QT = 16;
constexpr int KT = 16;
constexpr int NT = L_ / KT;      // 16 k-tiles
constexpr int QSTR = D_ + 4;     // 260 floats (odd multiple of 16B -> bank spread)
constexpr int SSTR = KT + 4;     // 20 floats

struct AttnSmem {
    float q[QT][QSTR];           // 16.6 KB
    float k[2][KT][QSTR];        // 33.3 KB (cp.async ping-pong)
    float ex[QT * KT][E_];       // 32 KB, XOR-swizzled at float4 granularity
    float s[H_][QT][SSTR];       // raw scores -> p*g
    float g[H_][QT][SSTR];       // sigmoid gate
    float m[H_][QT];
    float z[H_][QT];
    float r[H_][QT];
    float ew[H_][E_];
    float gw[H_][E_];
    float eowp[16][H_][2];       // paired eo_w
    float eb[H_];
    float gb[H_];
    float eob[E_];
};

__global__ __launch_bounds__(256, 2)
void edge_attn_kernel(const float* __restrict__ edge_x,
                      const float* __restrict__ e_w, const float* __restrict__ e_b,
                      const float* __restrict__ g_w, const float* __restrict__ g_b,
                      const float* __restrict__ eo_w, const float* __restrict__ eo_b,
                      float* __restrict__ edge_out)
{
    extern __shared__ char smem_raw[];
    AttnSmem& sm = *reinterpret_cast<AttnSmem*>(smem_raw);

    const int tid = threadIdx.x;
    const int b   = blockIdx.y;
    const int q0  = blockIdx.x * QT;
    const size_t bL = (size_t)b * L_;

    // --- weights / state init ---
    ((float*)sm.ew)[tid]  = e_w[tid];
    ((float*)sm.gw)[tid]  = g_w[tid];
    if (tid < 128) {
        int c2 = tid >> 3, hh = tid & 7;
        sm.eowp[c2][hh][0] = eo_w[(2 * c2 + 0) * H_ + hh];
        sm.eowp[c2][hh][1] = eo_w[(2 * c2 + 1) * H_ + hh];
    }
    if (tid < H_) { sm.eb[tid] = e_b[tid]; sm.gb[tid] = g_b[tid]; }
    if (tid < E_) { sm.eob[tid] = eo_b[tid]; }
    if (tid < H_ * QT) {
        ((float*)sm.m)[tid] = -1e30f;
        ((float*)sm.z)[tid] = 0.f;
    }

    // --- q tile (coalesced) ---
#pragma unroll
    for (int it = 0; it < 4; ++it) {
        int f4  = tid + it * 256;
        int row = f4 >> 6;
        int c   = (f4 & 63) * 4;
        *(float4*)&sm.q[row][c] =
            *(const float4*)&g_qkv[(bL + q0 + row) * (3 * D_) + c];
    }

    const int h    = tid >> 5;
    const int lane = tid & 31;
    const int qi   = tid >> 4;
    const int kk   = tid & 15;
    const int sw   = tid & 7;    // swizzle nibble for own ex row

    const unsigned ex_base = s2u(&sm.ex[0][0]);
    const unsigned exrow_a = ex_base + tid * 128;
    const unsigned q_a     = s2u(&sm.q[qi][0]);
    const unsigned ew_a    = s2u(&sm.ew[0][0]);
    const unsigned gw_a    = s2u(&sm.gw[0][0]);
    const unsigned eowp_a  = s2u(&sm.eowp[0][0][0]);
    const unsigned eob_a   = s2u(&sm.eob[0]);
    const unsigned srow_a  = s2u(&sm.s[h][0][0]);

    // coalesced ex mapping: f4 = it*256+tid -> (chunk, within) -> swizzled slot
    int ex_row[8];            // chunk*16 + (within>>3)
    int ex_col4[8];           // (within&7) ^ (row&7)
    int ex_chunk[8], ex_w4[8];
#pragma unroll
    for (int it = 0; it < 8; ++it) {
        int f4 = it * 256 + tid;
        int chunk  = f4 >> 7;
        int within = f4 & 127;
        int row    = chunk * 16 + (within >> 3);
        ex_chunk[it] = chunk;
        ex_w4[it]    = within;
        ex_row[it]   = row;
        ex_col4[it]  = (within & 7) ^ (row & 7);
    }

    // --- prologue: cp.async edge tile 0 + k[0] tile 0 ---
#pragma unroll
    for (int it = 0; it < 8; ++it)
        cp_async16(ex_base + ex_row[it] * 128 + ex_col4[it] * 16,
                   &edge_x[((bL + q0 + ex_chunk[it]) * L_ + 0) * E_ + ex_w4[it] * 4]);
#pragma unroll
    for (int it = 0; it < 4; ++it) {
        int f4  = tid + it * 256;
        int row = f4 >> 6;
        int c   = (f4 & 63) * 4;
        cp_async16(s2u(&sm.k[0][row][c]),
                   &g_qkv[(bL + row) * (3 * D_) + D_ + c]);
    }
    cp_commit();

    u64 acc2[QT];
#pragma unroll
    for (int i = 0; i < QT; i++) acc2[i] = 0ull;

    for (int i = 0; i < NT; i++) {
        const int k0 = i * KT;

        cp_wait0();
        __syncthreads();   // tile i (ex + k) resident; prev phase B done with s/g

        // v slice -> packed registers
        u64 v2[KT / 2];
#pragma unroll
        for (int t2 = 0; t2 < KT / 2; t2++) {
            float a = g_qkv[(bL + k0 + 2 * t2 + 0) * (3 * D_) + 2 * D_ + h * HD_ + lane];
            float c = g_qkv[(bL + k0 + 2 * t2 + 1) * (3 * D_) + 2 * D_ + h * HD_ + lane];
            v2[t2] = pk2(a, c);
        }

        const unsigned k_a = s2u(&sm.k[i & 1][kk][0]);

        // ---- Phase A (f32x2): thread owns pair (qi, kk) ----
        {
            u64 ev2[16];
#pragma unroll
            for (int j = 0; j < 8; ++j)
                lds_v2(ev2[2 * j], ev2[2 * j + 1], exrow_a + ((j ^ sw) * 16));

            float sh[H_];
#pragma unroll
            for (int hh = 0; hh < H_; ++hh) {
                u64 ea2 = 0ull, ga2 = 0ull, dot2 = 0ull;
                const unsigned ewr = ew_a + hh * 128;
                const unsigned gwr = gw_a + hh * 128;
                const unsigned qr  = q_a + hh * 128;
                const unsigned kr  = k_a + hh * 128;
#pragma unroll
                for (int j = 0; j < 8; ++j) {
                    u64 w0, w1;
                    lds_v2(w0, w1, ewr + j * 16);
                    ea2 = fma2(ev2[2 * j], w0, ea2);
                    ea2 = fma2(ev2[2 * j + 1], w1, ea2);
                    lds_v2(w0, w1, gwr + j * 16);
                    ga2 = fma2(ev2[2 * j], w0, ga2);
                    ga2 = fma2(ev2[2 * j + 1], w1, ga2);
                    u64 qa, qb, ka, kb;
                    lds_v2(qa, qb, qr + j * 16);
                    lds_v2(ka, kb, kr + j * 16);
                    dot2 = fma2(qa, ka, dot2);
                    dot2 = fma2(qb, kb, dot2);
                }
                float ea = hsum2(ea2) + sm.eb[hh];
                float ga = hsum2(ga2) + sm.gb[hh];
                float sv = hsum2(dot2) * SCALE_ + ea;
                sh[hh] = sv;
                sm.s[hh][qi][kk] = sv;
                sm.g[hh][qi][kk] = 1.0f / (1.0f + __expf(-ga));
            }

            // edge_out from RAW scores -> back into own (swizzled) ex row
            u64 shd[H_];
#pragma unroll
            for (int hh = 0; hh < H_; ++hh) shd[hh] = dup2(sh[hh]);
#pragma unroll
            for (int c2 = 0; c2 < 16; ++c2) {
                u64 a2 = lds_1(eob_a + c2 * 8);
                const unsigned wr = eowp_a + c2 * 64;
#pragma unroll
                for (int j = 0; j < 4; ++j) {
                    u64 w0, w1;
                    lds_v2(w0, w1, wr + j * 16);
                    a2 = fma2(shd[2 * j], w0, a2);
                    a2 = fma2(shd[2 * j + 1], w1, a2);
                }
                sts_1(exrow_a + (((c2 >> 1) ^ sw) * 16) + (c2 & 1) * 8, a2);
            }
        }
        __syncthreads();   // ex holds edge_out tile; s/g complete; k reads done

        // coalesced edge_out store (reads own cp.async slots -> safe reuse)
#pragma unroll
        for (int it = 0; it < 8; ++it) {
            float4 v4 = *(const float4*)&sm.ex[ex_row[it]][ex_col4[it] * 4];
            *(float4*)&edge_out[((bL + q0 + ex_chunk[it]) * L_ + k0) * E_
                                + ex_w4[it] * 4] = v4;
        }

        // prefetch tile i+1 (ex reuse is safe: same per-thread slots as reads above)
        if (i + 1 < NT) {
#pragma unroll
            for (int it = 0; it < 8; ++it)
                cp_async16(ex_base + ex_row[it] * 128 + ex_col4[it] * 16,
                           &edge_x[((bL + q0 + ex_chunk[it]) * L_ + k0 + KT) * E_
                                   + ex_w4[it] * 4]);
            float* kb = &sm.k[(i + 1) & 1][0][0];
#pragma unroll
            for (int it = 0; it < 4; ++it) {
                int f4  = tid + it * 256;
                int row = f4 >> 6;
                int c   = (f4 & 63) * 4;
                cp_async16(s2u(kb + row * QSTR + c),
                           &g_qkv[(bL + k0 + KT + row) * (3 * D_) + D_ + c]);
            }
        }
        cp_commit();

        // ---- Phase B: per-head online softmax + gated AV ----
        if (lane < QT) {
            const int q = lane;
            float mold = sm.m[h][q];
            float tmax = -1e30f;
#pragma unroll
            for (int t4 = 0; t4 < 4; t4++) {
                float4 sv = *(const float4*)&sm.s[h][q][t4 * 4];
                tmax = fmaxf(tmax, fmaxf(fmaxf(sv.x, sv.y), fmaxf(sv.z, sv.w)));
            }
            float mnew = fmaxf(mold, tmax);
            float r    = __expf(mold - mnew);
            float zs   = 0.f;
#pragma unroll
            for (int t4 = 0; t4 < 4; t4++) {
                float4 sv = *(const float4*)&sm.s[h][q][t4 * 4];
                float4 gv = *(const float4*)&sm.g[h][q][t4 * 4];
                float p0 = __expf(sv.x - mnew);
                float p1 = __expf(sv.y - mnew);
                float p2 = __expf(sv.z - mnew);
                float p3 = __expf(sv.w - mnew);
                zs += (p0 + p1) + (p2 + p3);           // Z ungated
                float4 o;
                o.x = p0 * gv.x; o.y = p1 * gv.y; o.z = p2 * gv.z; o.w = p3 * gv.w;
                *(float4*)&sm.s[h][q][t4 * 4] = o;     // numerator gated
            }
            sm.z[h][q] = sm.z[h][q] * r + zs;
            sm.m[h][q] = mnew;
            sm.r[h][q] = r;
        }
        __syncwarp();
#pragma unroll
        for (int q = 0; q < QT; q++) {
            u64 a2 = mul2(acc2[q], dup2(sm.r[h][q]));
            const unsigned sr = srow_a + q * (SSTR * 4);
#pragma unroll
            for (int j = 0; j < 4; ++j) {
                u64 p0, p1;
                lds_v2(p0, p1, sr + j * 16);
                a2 = fma2(p0, v2[2 * j], a2);
                a2 = fma2(p1, v2[2 * j + 1], a2);
            }
            acc2[q] = a2;
        }
    }

    // --- epilogue ---
#pragma unroll
    for (int q = 0; q < QT; q++) {
        g_aout[(bL + q0 + q) * D_ + h * HD_ + lane] = hsum2(acc2[q]) / sm.z[h][q];
    }
}

// ---------------------------------------------------------------------------
// kernel_launch
// ---------------------------------------------------------------------------
extern "C" void kernel_launch(void* const* d_in, const int* in_sizes, int n_in,
                              void* d_out, int out_size)
{
    const float* x       = (const float*)d_in[0];
    const float* edge_x  = (const float*)d_in[1];
    const float* in_w    = (const float*)d_in[2];
    const float* in_b    = (const float*)d_in[3];
    const float* out_w   = (const float*)d_in[4];
    const float* out_b   = (const float*)d_in[5];
    const float* e_w     = (const float*)d_in[6];
    const float* e_b     = (const float*)d_in[7];
    const float* g_w     = (const float*)d_in[8];
    const float* g_b     = (const float*)d_in[9];
    const float* eo_w    = (const float*)d_in[10];
    const float* eo_b    = (const float*)d_in[11];

    float* out0     = (float*)d_out;
    float* edge_out = out0 + (size_t)B_ * L_ * D_;

    float* qkv_ptr  = nullptr;
    float* aout_ptr = nullptr;
    cudaGetSymbolAddress((void**)&qkv_ptr,  g_qkv);
    cudaGetSymbolAddress((void**)&aout_ptr, g_aout);

    const int smem_bytes = (int)sizeof(AttnSmem);
    cudaFuncSetAttribute(edge_attn_kernel,
                         cudaFuncAttributeMaxDynamicSharedMemorySize, smem_bytes);

    sgemm_nt_bias<128, 128, 16><<<dim3(3 * D_ / 128, ROWS_ / 128), 256>>>(
        x, in_w, in_b, qkv_ptr, ROWS_, 3 * D_, D_);

    edge_attn_kernel<<<dim3(L_ / QT, B_), 256, smem_bytes>>>(
        edge_x, e_w, e_b, g_w, g_b, eo_w, eo_b, edge_out);

    sgemm_nt_bias<128, 128, 16><<<dim3(D_ / 128, ROWS_ / 128), 256>>>(
        aout_ptr, out_w, out_b, out0, ROWS_, D_, D_);
}

// round 6
// speedup vs baseline: 1.6051x; 1.2718x over previous
#include <cuda_runtime.h>
#include <math.h>

// ---------------------------------------------------------------------------
// Problem constants
// ---------------------------------------------------------------------------
constexpr int B_  = 32;
constexpr int L_  = 256;
constexpr int D_  = 256;
constexpr int E_  = 32;
constexpr int H_  = 8;
constexpr int HD_ = 32;
constexpr float SCALE_ = 0.17677669529663687f;  // 1/sqrt(32)

constexpr int ROWS_ = B_ * L_;   // 8192

// ---------------------------------------------------------------------------
// Device scratch
// ---------------------------------------------------------------------------
__device__ float g_qkv[ROWS_ * 3 * D_];   // [B*L, 768]  q|k|v
__device__ float g_aout[ROWS_ * D_];      // [B*L, 256]

// ---------------------------------------------------------------------------
// helpers
// ---------------------------------------------------------------------------
using u64 = unsigned long long;

__device__ __forceinline__ unsigned s2u(const void* p) {
    return (unsigned)__cvta_generic_to_shared(p);
}
__device__ __forceinline__ u64 fma2(u64 a, u64 b, u64 c) {
    u64 d; asm("fma.rn.f32x2 %0, %1, %2, %3;" : "=l"(d) : "l"(a), "l"(b), "l"(c));
    return d;
}
__device__ __forceinline__ u64 mul2(u64 a, u64 b) {
    u64 d; asm("mul.rn.f32x2 %0, %1, %2;" : "=l"(d) : "l"(a), "l"(b));
    return d;
}
__device__ __forceinline__ float hsum2(u64 a) {
    float lo, hi;
    asm("mov.b64 {%0,%1}, %2;" : "=f"(lo), "=f"(hi) : "l"(a));
    return lo + hi;
}
__device__ __forceinline__ u64 dup2(float x) {
    u64 d; asm("mov.b64 %0, {%1,%1};" : "=l"(d) : "f"(x)); return d;
}
__device__ __forceinline__ u64 pk2(float x, float y) {
    u64 d; asm("mov.b64 %0, {%1,%2};" : "=l"(d) : "f"(x), "f"(y)); return d;
}
__device__ __forceinline__ void cp_async16(unsigned smem_dst, const void* gmem_src) {
    asm volatile("cp.async.cg.shared.global [%0], [%1], 16;\n"
                 :: "r"(smem_dst), "l"(gmem_src) : "memory");
}
__device__ __forceinline__ void cp_commit() {
    asm volatile("cp.async.commit_group;\n" ::: "memory");
}
__device__ __forceinline__ void cp_wait0() {
    asm volatile("cp.async.wait_group 0;\n" ::: "memory");
}
// tf32 conversion + split (3xTF32)
__device__ __forceinline__ unsigned f2tf(float x) {
    unsigned r; asm("cvt.rna.tf32.f32 %0, %1;" : "=r"(r) : "f"(x)); return r;
}
__device__ __forceinline__ void tfsplit(float x, unsigned& hi, unsigned& lo) {
    hi = f2tf(x);
    lo = f2tf(x - __uint_as_float(hi));
}
// m16n8k8 tf32 MMA, D += A*B
__device__ __forceinline__ void mma8(float* d, const unsigned* a, const unsigned* b) {
    asm volatile(
        "mma.sync.aligned.m16n8k8.row.col.f32.tf32.tf32.f32 "
        "{%0,%1,%2,%3},{%4,%5,%6,%7},{%8,%9},{%0,%1,%2,%3};"
        : "+f"(d[0]), "+f"(d[1]), "+f"(d[2]), "+f"(d[3])
        : "r"(a[0]), "r"(a[1]), "r"(a[2]), "r"(a[3]), "r"(b[0]), "r"(b[1]));
}
__device__ __forceinline__ void mma3x(float* d, const unsigned* ah, const unsigned* al,
                                      const unsigned* bh, const unsigned* bl) {
    mma8(d, ah, bh);
    mma8(d, ah, bl);
    mma8(d, al, bh);
}

// ---------------------------------------------------------------------------
// Kernel 1/3: C = A @ W^T + bias (unchanged from r5)
// ---------------------------------------------------------------------------
template<int BM, int BN, int BK>
__global__ __launch_bounds__(256)
void sgemm_nt_bias(const float* __restrict__ A, const float* __restrict__ W,
                   const float* __restrict__ bias, float* __restrict__ C,
                   int M, int N, int K)
{
    __shared__ float As[BK][BM + 4];
    __shared__ float Bs[BK][BN + 4];

    const int tid = threadIdx.x;
    const int tx  = tid & 15;
    const int ty  = tid >> 4;
    const int m0  = blockIdx.y * BM;
    const int n0  = blockIdx.x * BN;

    u64 acc2[8][4];
#pragma unroll
    for (int i = 0; i < 8; i++)
#pragma unroll
        for (int j = 0; j < 4; j++) acc2[i][j] = 0ull;

    for (int k0 = 0; k0 < K; k0 += BK) {
#pragma unroll
        for (int it = 0; it < (BM * BK) / (256 * 4); ++it) {
            int f4  = tid + it * 256;
            int row = f4 >> 2;
            int c4  = (f4 & 3) * 4;
            float4 v = *(const float4*)&A[(size_t)(m0 + row) * K + k0 + c4];
            As[c4 + 0][row] = v.x; As[c4 + 1][row] = v.y;
            As[c4 + 2][row] = v.z; As[c4 + 3][row] = v.w;
        }
#pragma unroll
        for (int it = 0; it < (BN * BK) / (256 * 4); ++it) {
            int f4  = tid + it * 256;
            int row = f4 >> 2;
            int c4  = (f4 & 3) * 4;
            float4 v = *(const float4*)&W[(size_t)(n0 + row) * K + k0 + c4];
            Bs[c4 + 0][row] = v.x; Bs[c4 + 1][row] = v.y;
            Bs[c4 + 2][row] = v.z; Bs[c4 + 3][row] = v.w;
        }
        __syncthreads();

#pragma unroll
        for (int kk = 0; kk < BK; ++kk) {
            float a[8];
            *(float4*)&a[0] = *(const float4*)&As[kk][ty * 8];
            *(float4*)&a[4] = *(const float4*)&As[kk][ty * 8 + 4];
            u64 b2[4];
            const u64* bp = (const u64*)&Bs[kk][tx * 8];
            b2[0] = bp[0]; b2[1] = bp[1]; b2[2] = bp[2]; b2[3] = bp[3];
            u64 ad[8];
#pragma unroll
            for (int i = 0; i < 8; i++) ad[i] = dup2(a[i]);
#pragma unroll
            for (int i = 0; i < 8; i++)
#pragma unroll
                for (int j = 0; j < 4; j++)
                    acc2[i][j] = fma2(ad[i], b2[j], acc2[i][j]);
        }
        __syncthreads();
    }

#pragma unroll
    for (int i = 0; i < 8; i++) {
        int m = m0 + ty * 8 + i;
#pragma unroll
        for (int j4 = 0; j4 < 2; j4++) {
            int n = n0 + tx * 8 + j4 * 4;
            float l0, h0, l1, h1;
            asm("mov.b64 {%0,%1}, %2;" : "=f"(l0), "=f"(h0) : "l"(acc2[i][j4 * 2 + 0]));
            asm("mov.b64 {%0,%1}, %2;" : "=f"(l1), "=f"(h1) : "l"(acc2[i][j4 * 2 + 1]));
            float4 o;
            o.x = l0 + bias[n + 0];
            o.y = h0 + bias[n + 1];
            o.z = l1 + bias[n + 2];
            o.w = h1 + bias[n + 3];
            *(float4*)&C[(size_t)m * N + n] = o;
        }
    }
}

// ---------------------------------------------------------------------------
// Kernel 2: fused edge attention (v6 — tf32 MMA phase A)
// ---------------------------------------------------------------------------
constexpr int QT = 16;
constexpr int KT = 16;
constexpr int NT = L_ / KT;        // 16 k-tiles
constexpr int QSTR  = D_ + 4;      // 260
constexpr int SROWQ = 20;          // words per q-row in s/g
constexpr int SROWH = QT * SROWQ + 4;  // 324 words per head (stride%32==4 -> spread)

struct AttnSmem {
    float q[QT][QSTR];            // 16.6 KB
    float k[KT][QSTR];            // 16.6 KB (single buffer)
    float ex[QT * KT][E_];        // 32 KB, XOR-swizzled at float4 granularity
    float s[H_ * SROWH];          // raw scores (pre-filled with e, then raw, then p*g)
    float g[H_ * SROWH];          // sigmoid gate
    float m[H_][QT];
    float z[H_][QT];
    float r[H_][QT];
    float w2hi[16][36];           // rows 0..7 = e_w, 8..15 = g_w (tf32 hi)
    float w2lo[16][36];           // residual
    float eowhi[E_][9];           // eo_w [E][H] tf32 hi
    float eowlo[E_][9];
    float eb[H_];
    float gb[H_];
    float eob[E_];
};

// swizzled ex element index (floats)
__device__ __forceinline__ int ex_idx(int row, int col) {
    return row * 32 + (((col >> 2) ^ (row & 7)) << 2) + (col & 3);
}

__global__ __launch_bounds__(256, 2)
void edge_attn_kernel(const float* __restrict__ edge_x,
                      const float* __restrict__ e_w, const float* __restrict__ e_b,
                      const float* __restrict__ g_w, const float* __restrict__ g_b,
                      const float* __restrict__ eo_w, const float* __restrict__ eo_b,
                      float* __restrict__ edge_out)
{
    extern __shared__ char smem_raw[];
    AttnSmem& sm = *reinterpret_cast<AttnSmem*>(smem_raw);

    const int tid = threadIdx.x;
    const int b   = blockIdx.y;
    const int q0  = blockIdx.x * QT;
    const size_t bL = (size_t)b * L_;

    const int w    = tid >> 5;      // warp id = head id
    const int lane = tid & 31;
    const int gid  = lane >> 2;     // 0..7
    const int ctg  = lane & 3;      // 0..3

    // --- weight presplit / state init ---
#pragma unroll
    for (int it = 0; it < 2; ++it) {
        int idx = tid + it * 256;             // 0..511
        int rr = idx >> 5, cc = idx & 31;
        float val = (rr < 8) ? e_w[rr * E_ + cc] : g_w[(rr - 8) * E_ + cc];
        unsigned hi, lo; tfsplit(val, hi, lo);
        sm.w2hi[rr][cc] = __uint_as_float(hi);
        sm.w2lo[rr][cc] = __uint_as_float(lo);
    }
    {
        int n = tid >> 3, hc = tid & 7;
        unsigned hi, lo; tfsplit(eo_w[n * H_ + hc], hi, lo);
        sm.eowhi[n][hc] = __uint_as_float(hi);
        sm.eowlo[n][hc] = __uint_as_float(lo);
    }
    if (tid < H_) { sm.eb[tid] = e_b[tid]; sm.gb[tid] = g_b[tid]; }
    if (tid < E_) { sm.eob[tid] = eo_b[tid]; }
    if (tid < H_ * QT) {
        ((float*)sm.m)[tid] = -1e30f;
        ((float*)sm.z)[tid] = 0.f;
    }

    // --- q tile (coalesced) ---
#pragma unroll
    for (int it = 0; it < 4; ++it) {
        int f4  = tid + it * 256;
        int row = f4 >> 6;
        int c   = (f4 & 63) * 4;
        *(float4*)&sm.q[row][c] =
            *(const float4*)&g_qkv[(bL + q0 + row) * (3 * D_) + c];
    }

    // coalesced ex staging mapping (same as r5)
    const unsigned ex_base = s2u(&sm.ex[0][0]);
    int ex_row[8], ex_col4[8], ex_chunk[8], ex_w4[8];
#pragma unroll
    for (int it = 0; it < 8; ++it) {
        int f4 = it * 256 + tid;
        int chunk  = f4 >> 7;
        int within = f4 & 127;
        int row    = chunk * 16 + (within >> 3);
        ex_chunk[it] = chunk;
        ex_w4[it]    = within;
        ex_row[it]   = row;
        ex_col4[it]  = (within & 7) ^ (row & 7);
    }

    // --- prologue: cp.async ex tile 0 + k tile 0 ---
#pragma unroll
    for (int it = 0; it < 8; ++it)
        cp_async16(ex_base + ex_row[it] * 128 + ex_col4[it] * 16,
                   &edge_x[((bL + q0 + ex_chunk[it]) * L_ + 0) * E_ + ex_w4[it] * 4]);
#pragma unroll
    for (int it = 0; it < 4; ++it) {
        int f4  = tid + it * 256;
        int row = f4 >> 6;
        int c   = (f4 & 63) * 4;
        cp_async16(s2u(&sm.k[row][c]),
                   &g_qkv[(bL + row) * (3 * D_) + D_ + c]);
    }
    cp_commit();

    u64 acc2[QT];
#pragma unroll
    for (int i = 0; i < QT; i++) acc2[i] = 0ull;

    const u64 scl2 = dup2(SCALE_);

    for (int i = 0; i < NT; i++) {
        const int k0 = i * KT;

        cp_wait0();
        __syncthreads();          // bar1: ex + k tile i resident; prev phase B done

        // v slice -> packed registers (for phase B)
        u64 v2[KT / 2];
#pragma unroll
        for (int t2 = 0; t2 < KT / 2; t2++) {
            float a = g_qkv[(bL + k0 + 2 * t2 + 0) * (3 * D_) + 2 * D_ + w * HD_ + lane];
            float c = g_qkv[(bL + k0 + 2 * t2 + 1) * (3 * D_) + 2 * D_ + w * HD_ + lane];
            v2[t2] = pk2(a, c);
        }

        // ===== scores MMA: warp w computes head w, S = Q_w @ K_w^T =====
        float ds[2][4];
#pragma unroll
        for (int nt = 0; nt < 2; nt++)
#pragma unroll
            for (int e = 0; e < 4; e++) ds[nt][e] = 0.f;
#pragma unroll
        for (int ks = 0; ks < 4; ks++) {
            const int qc = w * HD_ + ks * 8 + ctg;
            unsigned ah[4], al[4];
            tfsplit(sm.q[gid][qc],         ah[0], al[0]);
            tfsplit(sm.q[gid + 8][qc],     ah[1], al[1]);
            tfsplit(sm.q[gid][qc + 4],     ah[2], al[2]);
            tfsplit(sm.q[gid + 8][qc + 4], ah[3], al[3]);
#pragma unroll
            for (int nt = 0; nt < 2; nt++) {
                unsigned bh[2], bl[2];
                tfsplit(sm.k[nt * 8 + gid][qc],     bh[0], bl[0]);
                tfsplit(sm.k[nt * 8 + gid][qc + 4], bh[1], bl[1]);
                mma3x(ds[nt], ah, al, bh, bl);
            }
        }

        // ===== GEMM-2: e/g projection, EG[256,16] = EX[256,32] @ W2^T =====
        // warp handles m-tiles {2w, 2w+1}; scatter e->s (with eb), g->g (sigmoid)
#pragma unroll
        for (int mtl = 0; mtl < 2; mtl++) {
            const int mt = 2 * w + mtl;
            const int m0 = mt * 16;
            float d2[2][4];
#pragma unroll
            for (int nt = 0; nt < 2; nt++)
#pragma unroll
                for (int e = 0; e < 4; e++) d2[nt][e] = 0.f;
#pragma unroll
            for (int ks = 0; ks < 4; ks++) {
                const int c = ks * 8 + ctg;
                unsigned ah[4], al[4];
                tfsplit(((const float*)sm.ex)[ex_idx(m0 + gid,     c)],     ah[0], al[0]);
                tfsplit(((const float*)sm.ex)[ex_idx(m0 + gid + 8, c)],     ah[1], al[1]);
                tfsplit(((const float*)sm.ex)[ex_idx(m0 + gid,     c + 4)], ah[2], al[2]);
                tfsplit(((const float*)sm.ex)[ex_idx(m0 + gid + 8, c + 4)], ah[3], al[3]);
#pragma unroll
                for (int nt = 0; nt < 2; nt++) {
                    unsigned bh[2], bl[2];
                    bh[0] = __float_as_uint(sm.w2hi[nt * 8 + gid][c]);
                    bh[1] = __float_as_uint(sm.w2hi[nt * 8 + gid][c + 4]);
                    bl[0] = __float_as_uint(sm.w2lo[nt * 8 + gid][c]);
                    bl[1] = __float_as_uint(sm.w2lo[nt * 8 + gid][c + 4]);
                    mma3x(d2[nt], ah, al, bh, bl);
                }
            }
            // scatter: e half (nt=0) with eb into sm.s ; gate (nt=1) sigmoid into sm.g
            const int h0 = 2 * ctg, h1 = 2 * ctg + 1;
            const int base0 = h0 * SROWH + mt * SROWQ;
            const int base1 = h1 * SROWH + mt * SROWQ;
            sm.s[base0 + gid]     = d2[0][0] + sm.eb[h0];
            sm.s[base1 + gid]     = d2[0][1] + sm.eb[h1];
            sm.s[base0 + gid + 8] = d2[0][2] + sm.eb[h0];
            sm.s[base1 + gid + 8] = d2[0][3] + sm.eb[h1];
            sm.g[base0 + gid]     = 1.f / (1.f + __expf(-(d2[1][0] + sm.gb[h0])));
            sm.g[base1 + gid]     = 1.f / (1.f + __expf(-(d2[1][1] + sm.gb[h1])));
            sm.g[base0 + gid + 8] = 1.f / (1.f + __expf(-(d2[1][2] + sm.gb[h0])));
            sm.g[base1 + gid + 8] = 1.f / (1.f + __expf(-(d2[1][3] + sm.gb[h1])));
        }
        __syncthreads();          // bar2: e/g in smem

        // ===== score merge: raw = dot*SCALE + e, write into sm.s =====
#pragma unroll
        for (int nt = 0; nt < 2; nt++) {
            const int kc = nt * 8 + 2 * ctg;
            u64* p01 = (u64*)&sm.s[w * SROWH + gid * SROWQ + kc];
            u64* p23 = (u64*)&sm.s[w * SROWH + (gid + 8) * SROWQ + kc];
            *p01 = fma2(pk2(ds[nt][0], ds[nt][1]), scl2, *p01);
            *p23 = fma2(pk2(ds[nt][2], ds[nt][3]), scl2, *p23);
        }
        __syncthreads();          // bar3: raw scores complete

        // ===== GEMM-3: edge_out EO[256,32] = S'[256,8] @ EOW^T, K=8 =====
        unsigned b3h[4][2], b3l[4][2];
#pragma unroll
        for (int nt = 0; nt < 4; nt++) {
            b3h[nt][0] = __float_as_uint(sm.eowhi[nt * 8 + gid][ctg]);
            b3h[nt][1] = __float_as_uint(sm.eowhi[nt * 8 + gid][ctg + 4]);
            b3l[nt][0] = __float_as_uint(sm.eowlo[nt * 8 + gid][ctg]);
            b3l[nt][1] = __float_as_uint(sm.eowlo[nt * 8 + gid][ctg + 4]);
        }
#pragma unroll
        for (int mtl = 0; mtl < 2; mtl++) {
            const int mt = 2 * w + mtl;
            unsigned ah[4], al[4];
            tfsplit(sm.s[ctg * SROWH + mt * SROWQ + gid],           ah[0], al[0]);
            tfsplit(sm.s[ctg * SROWH + mt * SROWQ + gid + 8],       ah[1], al[1]);
            tfsplit(sm.s[(ctg + 4) * SROWH + mt * SROWQ + gid],     ah[2], al[2]);
            tfsplit(sm.s[(ctg + 4) * SROWH + mt * SROWQ + gid + 8], ah[3], al[3]);
            float d3[4][4];
#pragma unroll
            for (int nt = 0; nt < 4; nt++) {
#pragma unroll
                for (int e = 0; e < 4; e++) d3[nt][e] = 0.f;
                mma3x(d3[nt], ah, al, b3h[nt], b3l[nt]);
            }
            // store to ex (swizzled), + bias
#pragma unroll
            for (int nt = 0; nt < 4; nt++) {
                const int col = nt * 8 + 2 * ctg;
                const int row = mt * 16 + gid;
                float o0 = d3[nt][0] + sm.eob[col];
                float o1 = d3[nt][1] + sm.eob[col + 1];
                float o2 = d3[nt][2] + sm.eob[col];
                float o3 = d3[nt][3] + sm.eob[col + 1];
                *(u64*)&((float*)sm.ex)[ex_idx(row, col)]     = pk2(o0, o1);
                *(u64*)&((float*)sm.ex)[ex_idx(row + 8, col)] = pk2(o2, o3);
            }
        }
        __syncthreads();          // bar4: ex = edge_out tile; s stable for phase B

        // coalesced edge_out store (each thread reads its own staging slots)
#pragma unroll
        for (int it = 0; it < 8; ++it) {
            float4 v4 = *(const float4*)&((const float*)sm.ex)
                            [ex_row[it] * 32 + ex_col4[it] * 4];
            *(float4*)&edge_out[((bL + q0 + ex_chunk[it]) * L_ + k0) * E_
                                + ex_w4[it] * 4] = v4;
        }

        // prefetch tile i+1
        if (i + 1 < NT) {
#pragma unroll
            for (int it = 0; it < 8; ++it)
                cp_async16(ex_base + ex_row[it] * 128 + ex_col4[it] * 16,
                           &edge_x[((bL + q0 + ex_chunk[it]) * L_ + k0 + KT) * E_
                                   + ex_w4[it] * 4]);
#pragma unroll
            for (int it = 0; it < 4; ++it) {
                int f4  = tid + it * 256;
                int row = f4 >> 6;
                int c   = (f4 & 63) * 4;
                cp_async16(s2u(&sm.k[row][c]),
                           &g_qkv[(bL + k0 + KT + row) * (3 * D_) + D_ + c]);
            }
        }
        cp_commit();

        // ===== Phase B: per-head online softmax + gated AV =====
        if (lane < QT) {
            const int q = lane;
            float* srow = &sm.s[w * SROWH + q * SROWQ];
            float* grow = &sm.g[w * SROWH + q * SROWQ];
            float mold = sm.m[w][q];
            float tmax = -1e30f;
#pragma unroll
            for (int t4 = 0; t4 < 4; t4++) {
                float4 sv = *(const float4*)&srow[t4 * 4];
                tmax = fmaxf(tmax, fmaxf(fmaxf(sv.x, sv.y), fmaxf(sv.z, sv.w)));
            }
            float mnew = fmaxf(mold, tmax);
            float r    = __expf(mold - mnew);
            float zs   = 0.f;
#pragma unroll
            for (int t4 = 0; t4 < 4; t4++) {
                float4 sv = *(const float4*)&srow[t4 * 4];
                float4 gv = *(const float4*)&grow[t4 * 4];
                float p0 = __expf(sv.x - mnew);
                float p1 = __expf(sv.y - mnew);
                float p2 = __expf(sv.z - mnew);
                float p3 = __expf(sv.w - mnew);
                zs += (p0 + p1) + (p2 + p3);           // Z ungated
                float4 o;
                o.x = p0 * gv.x; o.y = p1 * gv.y; o.z = p2 * gv.z; o.w = p3 * gv.w;
                *(float4*)&srow[t4 * 4] = o;           // numerator gated
            }
            sm.z[w][q] = sm.z[w][q] * r + zs;
            sm.m[w][q] = mnew;
            sm.r[w][q] = r;
        }
        __syncwarp();
#pragma unroll
        for (int q = 0; q < QT; q++) {
            u64 a2 = mul2(acc2[q], dup2(sm.r[w][q]));
            const u64* prow = (const u64*)&sm.s[w * SROWH + q * SROWQ];
#pragma unroll
            for (int j = 0; j < 4; ++j) {
                a2 = fma2(prow[2 * j],     v2[2 * j],     a2);
                a2 = fma2(prow[2 * j + 1], v2[2 * j + 1], a2);
            }
            acc2[q] = a2;
        }
    }

    // --- epilogue ---
#pragma unroll
    for (int q = 0; q < QT; q++) {
        g_aout[(bL + q0 + q) * D_ + w * HD_ + lane] = hsum2(acc2[q]) / sm.z[w][q];
    }
}

// ---------------------------------------------------------------------------
// kernel_launch
// ---------------------------------------------------------------------------
extern "C" void kernel_launch(void* const* d_in, const int* in_sizes, int n_in,
                              void* d_out, int out_size)
{
    const float* x       = (const float*)d_in[0];
    const float* edge_x  = (const float*)d_in[1];
    const float* in_w    = (const float*)d_in[2];
    const float* in_b    = (const float*)d_in[3];
    const float* out_w   = (const float*)d_in[4];
    const float* out_b   = (const float*)d_in[5];
    const float* e_w     = (const float*)d_in[6];
    const float* e_b     = (const float*)d_in[7];
    const float* g_w     = (const float*)d_in[8];
    const float* g_b     = (const float*)d_in[9];
    const float* eo_w    = (const float*)d_in[10];
    const float* eo_b    = (const float*)d_in[11];

    float* out0     = (float*)d_out;
    float* edge_out = out0 + (size_t)B_ * L_ * D_;

    float* qkv_ptr  = nullptr;
    float* aout_ptr = nullptr;
    cudaGetSymbolAddress((void**)&qkv_ptr,  g_qkv);
    cudaGetSymbolAddress((void**)&aout_ptr, g_aout);

    const int smem_bytes = (int)sizeof(AttnSmem);
    cudaFuncSetAttribute(edge_attn_kernel,
                         cudaFuncAttributeMaxDynamicSharedMemorySize, smem_bytes);

    sgemm_nt_bias<128, 128, 16><<<dim3(3 * D_ / 128, ROWS_ / 128), 256>>>(
        x, in_w, in_b, qkv_ptr, ROWS_, 3 * D_, D_);

    edge_attn_kernel<<<dim3(L_ / QT, B_), 256, smem_bytes>>>(
        edge_x, e_w, e_b, g_w, g_b, eo_w, eo_b, edge_out);

    sgemm_nt_bias<128, 128, 16><<<dim3(D_ / 128, ROWS_ / 128), 256>>>(
        aout_ptr, out_w, out_b, out0, ROWS_, D_, D_);
}

// round 7
// speedup vs baseline: 1.7792x; 1.1085x over previous
#include <cuda_runtime.h>
#include <math.h>

// ---------------------------------------------------------------------------
// Problem constants
// ---------------------------------------------------------------------------
constexpr int B_  = 32;
constexpr int L_  = 256;
constexpr int D_  = 256;
constexpr int E_  = 32;
constexpr int H_  = 8;
constexpr int HD_ = 32;
constexpr float SCALE_ = 0.17677669529663687f;  // 1/sqrt(32)

constexpr int ROWS_ = B_ * L_;   // 8192

// ---------------------------------------------------------------------------
// Device scratch
// ---------------------------------------------------------------------------
__device__ float g_qkv[ROWS_ * 3 * D_];   // [B*L, 768]  q|k|v
__device__ float g_aout[ROWS_ * D_];      // [B*L, 256]

// ---------------------------------------------------------------------------
// helpers
// ---------------------------------------------------------------------------
using u64 = unsigned long long;

__device__ __forceinline__ unsigned s2u(const void* p) {
    return (unsigned)__cvta_generic_to_shared(p);
}
__device__ __forceinline__ u64 fma2(u64 a, u64 b, u64 c) {
    u64 d; asm("fma.rn.f32x2 %0, %1, %2, %3;" : "=l"(d) : "l"(a), "l"(b), "l"(c));
    return d;
}
__device__ __forceinline__ u64 mul2(u64 a, u64 b) {
    u64 d; asm("mul.rn.f32x2 %0, %1, %2;" : "=l"(d) : "l"(a), "l"(b));
    return d;
}
__device__ __forceinline__ float hsum2(u64 a) {
    float lo, hi;
    asm("mov.b64 {%0,%1}, %2;" : "=f"(lo), "=f"(hi) : "l"(a));
    return lo + hi;
}
__device__ __forceinline__ u64 dup2(float x) {
    u64 d; asm("mov.b64 %0, {%1,%1};" : "=l"(d) : "f"(x)); return d;
}
__device__ __forceinline__ u64 pk2(float x, float y) {
    u64 d; asm("mov.b64 %0, {%1,%2};" : "=l"(d) : "f"(x), "f"(y)); return d;
}
__device__ __forceinline__ void cp_async16(unsigned smem_dst, const void* gmem_src) {
    asm volatile("cp.async.cg.shared.global [%0], [%1], 16;\n"
                 :: "r"(smem_dst), "l"(gmem_src) : "memory");
}
__device__ __forceinline__ void cp_commit() {
    asm volatile("cp.async.commit_group;\n" ::: "memory");
}
__device__ __forceinline__ void cp_wait0() {
    asm volatile("cp.async.wait_group 0;\n" ::: "memory");
}
// tf32 conversion + split (3xTF32)
__device__ __forceinline__ unsigned f2tf(float x) {
    unsigned r; asm("cvt.rna.tf32.f32 %0, %1;" : "=r"(r) : "f"(x)); return r;
}
__device__ __forceinline__ void tfsplit(float x, unsigned& hi, unsigned& lo) {
    hi = f2tf(x);
    lo = f2tf(x - __uint_as_float(hi));
}
// m16n8k8 tf32 MMA, D += A*B
__device__ __forceinline__ void mma8(float* d, const unsigned* a, const unsigned* b) {
    asm volatile(
        "mma.sync.aligned.m16n8k8.row.col.f32.tf32.tf32.f32 "
        "{%0,%1,%2,%3},{%4,%5,%6,%7},{%8,%9},{%0,%1,%2,%3};"
        : "+f"(d[0]), "+f"(d[1]), "+f"(d[2]), "+f"(d[3])
        : "r"(a[0]), "r"(a[1]), "r"(a[2]), "r"(a[3]), "r"(b[0]), "r"(b[1]));
}
__device__ __forceinline__ void mma3x(float* d, const unsigned* ah, const unsigned* al,
                                      const unsigned* bh, const unsigned* bl) {
    mma8(d, ah, bh);
    mma8(d, ah, bl);
    mma8(d, al, bh);
}

// ---------------------------------------------------------------------------
// Kernel 1/3: tf32 tensor-core GEMM, C = A @ W^T + bias (3xTF32)
// BM=128, BN=64, BK=32, 256 threads, warp grid 4m x 2n, warp tile 32x32.
// ---------------------------------------------------------------------------
constexpr int GBM = 128;
constexpr int GBN = 64;
constexpr int GBK = 32;
constexpr int GSTR = GBK + 4;    // 36: bank = (4*row + col) % 32 -> conflict-free frags

struct GemmSmem {
    float As[2][GBM][GSTR];
    float Ws[2][GBN][GSTR];
};

__global__ __launch_bounds__(256, 2)
void tf32_gemm_nt_bias(const float* __restrict__ A, const float* __restrict__ W,
                       const float* __restrict__ bias, float* __restrict__ C,
                       int M, int N, int K)
{
    extern __shared__ char smem_raw[];
    GemmSmem& sm = *reinterpret_cast<GemmSmem*>(smem_raw);

    const int tid  = threadIdx.x;
    const int w    = tid >> 5;
    const int lane = tid & 31;
    const int gid  = lane >> 2;
    const int ctg  = lane & 3;
    const int wm   = w >> 1;        // 0..3
    const int wn   = w & 1;         // 0..1
    const int m0   = blockIdx.y * GBM;
    const int n0   = blockIdx.x * GBN;

    const int NIT = K / GBK;

    // --- stage tile 0 ---
#pragma unroll
    for (int it = 0; it < 4; ++it) {
        int idx = tid + it * 256;     // 0..1023
        int row = idx >> 3;
        int c4  = (idx & 7) * 4;
        cp_async16(s2u(&sm.As[0][row][c4]), &A[(size_t)(m0 + row) * K + c4]);
    }
#pragma unroll
    for (int it = 0; it < 2; ++it) {
        int idx = tid + it * 256;     // 0..511
        int row = idx >> 3;
        int c4  = (idx & 7) * 4;
        cp_async16(s2u(&sm.Ws[0][row][c4]), &W[(size_t)(n0 + row) * K + c4]);
    }
    cp_commit();

    float acc[2][4][4];
#pragma unroll
    for (int mt = 0; mt < 2; mt++)
#pragma unroll
        for (int nt = 0; nt < 4; nt++)
#pragma unroll
            for (int e = 0; e < 4; e++) acc[mt][nt][e] = 0.f;

    for (int i = 0; i < NIT; i++) {
        const int buf = i & 1;
        cp_wait0();
        __syncthreads();

        // prefetch next tile into other buffer
        if (i + 1 < NIT) {
            const int k0 = (i + 1) * GBK;
#pragma unroll
            for (int it = 0; it < 4; ++it) {
                int idx = tid + it * 256;
                int row = idx >> 3;
                int c4  = (idx & 7) * 4;
                cp_async16(s2u(&sm.As[buf ^ 1][row][c4]),
                           &A[(size_t)(m0 + row) * K + k0 + c4]);
            }
#pragma unroll
            for (int it = 0; it < 2; ++it) {
                int idx = tid + it * 256;
                int row = idx >> 3;
                int c4  = (idx & 7) * 4;
                cp_async16(s2u(&sm.Ws[buf ^ 1][row][c4]),
                           &W[(size_t)(n0 + row) * K + k0 + c4]);
            }
        }
        cp_commit();

        // compute on buf
#pragma unroll
        for (int ks = 0; ks < 4; ks++) {
            const int kc = ks * 8 + ctg;
            unsigned ah[2][4], al[2][4];
#pragma unroll
            for (int mt = 0; mt < 2; mt++) {
                const int r0 = wm * 32 + mt * 16 + gid;
                tfsplit(sm.As[buf][r0][kc],         ah[mt][0], al[mt][0]);
                tfsplit(sm.As[buf][r0 + 8][kc],     ah[mt][1], al[mt][1]);
                tfsplit(sm.As[buf][r0][kc + 4],     ah[mt][2], al[mt][2]);
                tfsplit(sm.As[buf][r0 + 8][kc + 4], ah[mt][3], al[mt][3]);
            }
#pragma unroll
            for (int nt = 0; nt < 4; nt++) {
                const int nr = wn * 32 + nt * 8 + gid;
                unsigned bh[2], bl[2];
                tfsplit(sm.Ws[buf][nr][kc],     bh[0], bl[0]);
                tfsplit(sm.Ws[buf][nr][kc + 4], bh[1], bl[1]);
                mma3x(acc[0][nt], ah[0], al[0], bh, bl);
                mma3x(acc[1][nt], ah[1], al[1], bh, bl);
            }
        }
        __syncthreads();
    }

    // --- epilogue: + bias, u64 paired stores ---
#pragma unroll
    for (int mt = 0; mt < 2; mt++) {
        const int row = m0 + wm * 32 + mt * 16 + gid;
#pragma unroll
        for (int nt = 0; nt < 4; nt++) {
            const int col = n0 + wn * 32 + nt * 8 + 2 * ctg;
            const float b0 = bias[col], b1 = bias[col + 1];
            *(u64*)&C[(size_t)row * N + col] =
                pk2(acc[mt][nt][0] + b0, acc[mt][nt][1] + b1);
            *(u64*)&C[(size_t)(row + 8) * N + col] =
                pk2(acc[mt][nt][2] + b0, acc[mt][nt][3] + b1);
        }
    }
}

// ---------------------------------------------------------------------------
// Kernel 2: fused edge attention (v6 — unchanged from round 6)
// ---------------------------------------------------------------------------
constexpr int QT = 16;
constexpr int KT = 16;
constexpr int NT = L_ / KT;        // 16 k-tiles
constexpr int QSTR  = D_ + 4;      // 260
constexpr int SROWQ = 20;          // words per q-row in s/g
constexpr int SROWH = QT * SROWQ + 4;  // 324 words per head

struct AttnSmem {
    float q[QT][QSTR];
    float k[KT][QSTR];
    float ex[QT * KT][E_];        // XOR-swizzled at float4 granularity
    float s[H_ * SROWH];
    float g[H_ * SROWH];
    float m[H_][QT];
    float z[H_][QT];
    float r[H_][QT];
    float w2hi[16][36];
    float w2lo[16][36];
    float eowhi[E_][9];
    float eowlo[E_][9];
    float eb[H_];
    float gb[H_];
    float eob[E_];
};

__device__ __forceinline__ int ex_idx(int row, int col) {
    return row * 32 + (((col >> 2) ^ (row & 7)) << 2) + (col & 3);
}

__global__ __launch_bounds__(256, 2)
void edge_attn_kernel(const float* __restrict__ edge_x,
                      const float* __restrict__ e_w, const float* __restrict__ e_b,
                      const float* __restrict__ g_w, const float* __restrict__ g_b,
                      const float* __restrict__ eo_w, const float* __restrict__ eo_b,
                      float* __restrict__ edge_out)
{
    extern __shared__ char smem_raw[];
    AttnSmem& sm = *reinterpret_cast<AttnSmem*>(smem_raw);

    const int tid = threadIdx.x;
    const int b   = blockIdx.y;
    const int q0  = blockIdx.x * QT;
    const size_t bL = (size_t)b * L_;

    const int w    = tid >> 5;
    const int lane = tid & 31;
    const int gid  = lane >> 2;
    const int ctg  = lane & 3;

#pragma unroll
    for (int it = 0; it < 2; ++it) {
        int idx = tid + it * 256;
        int rr = idx >> 5, cc = idx & 31;
        float val = (rr < 8) ? e_w[rr * E_ + cc] : g_w[(rr - 8) * E_ + cc];
        unsigned hi, lo; tfsplit(val, hi, lo);
        sm.w2hi[rr][cc] = __uint_as_float(hi);
        sm.w2lo[rr][cc] = __uint_as_float(lo);
    }
    {
        int n = tid >> 3, hc = tid & 7;
        unsigned hi, lo; tfsplit(eo_w[n * H_ + hc], hi, lo);
        sm.eowhi[n][hc] = __uint_as_float(hi);
        sm.eowlo[n][hc] = __uint_as_float(lo);
    }
    if (tid < H_) { sm.eb[tid] = e_b[tid]; sm.gb[tid] = g_b[tid]; }
    if (tid < E_) { sm.eob[tid] = eo_b[tid]; }
    if (tid < H_ * QT) {
        ((float*)sm.m)[tid] = -1e30f;
        ((float*)sm.z)[tid] = 0.f;
    }

#pragma unroll
    for (int it = 0; it < 4; ++it) {
        int f4  = tid + it * 256;
        int row = f4 >> 6;
        int c   = (f4 & 63) * 4;
        *(float4*)&sm.q[row][c] =
            *(const float4*)&g_qkv[(bL + q0 + row) * (3 * D_) + c];
    }

    const unsigned ex_base = s2u(&sm.ex[0][0]);
    int ex_row[8], ex_col4[8], ex_chunk[8], ex_w4[8];
#pragma unroll
    for (int it = 0; it < 8; ++it) {
        int f4 = it * 256 + tid;
        int chunk  = f4 >> 7;
        int within = f4 & 127;
        int row    = chunk * 16 + (within >> 3);
        ex_chunk[it] = chunk;
        ex_w4[it]    = within;
        ex_row[it]   = row;
        ex_col4[it]  = (within & 7) ^ (row & 7);
    }

#pragma unroll
    for (int it = 0; it < 8; ++it)
        cp_async16(ex_base + ex_row[it] * 128 + ex_col4[it] * 16,
                   &edge_x[((bL + q0 + ex_chunk[it]) * L_ + 0) * E_ + ex_w4[it] * 4]);
#pragma unroll
    for (int it = 0; it < 4; ++it) {
        int f4  = tid + it * 256;
        int row = f4 >> 6;
        int c   = (f4 & 63) * 4;
        cp_async16(s2u(&sm.k[row][c]),
                   &g_qkv[(bL + row) * (3 * D_) + D_ + c]);
    }
    cp_commit();

    u64 acc2[QT];
#pragma unroll
    for (int i = 0; i < QT; i++) acc2[i] = 0ull;

    const u64 scl2 = dup2(SCALE_);

    for (int i = 0; i < NT; i++) {
        const int k0 = i * KT;

        cp_wait0();
        __syncthreads();

        u64 v2[KT / 2];
#pragma unroll
        for (int t2 = 0; t2 < KT / 2; t2++) {
            float a = g_qkv[(bL + k0 + 2 * t2 + 0) * (3 * D_) + 2 * D_ + w * HD_ + lane];
            float c = g_qkv[(bL + k0 + 2 * t2 + 1) * (3 * D_) + 2 * D_ + w * HD_ + lane];
            v2[t2] = pk2(a, c);
        }

        float ds[2][4];
#pragma unroll
        for (int nt = 0; nt < 2; nt++)
#pragma unroll
            for (int e = 0; e < 4; e++) ds[nt][e] = 0.f;
#pragma unroll
        for (int ks = 0; ks < 4; ks++) {
            const int qc = w * HD_ + ks * 8 + ctg;
            unsigned ah[4], al[4];
            tfsplit(sm.q[gid][qc],         ah[0], al[0]);
            tfsplit(sm.q[gid + 8][qc],     ah[1], al[1]);
            tfsplit(sm.q[gid][qc + 4],     ah[2], al[2]);
            tfsplit(sm.q[gid + 8][qc + 4], ah[3], al[3]);
#pragma unroll
            for (int nt = 0; nt < 2; nt++) {
                unsigned bh[2], bl[2];
                tfsplit(sm.k[nt * 8 + gid][qc],     bh[0], bl[0]);
                tfsplit(sm.k[nt * 8 + gid][qc + 4], bh[1], bl[1]);
                mma3x(ds[nt], ah, al, bh, bl);
            }
        }

#pragma unroll
        for (int mtl = 0; mtl < 2; mtl++) {
            const int mt = 2 * w + mtl;
            const int m0 = mt * 16;
            float d2[2][4];
#pragma unroll
            for (int nt = 0; nt < 2; nt++)
#pragma unroll
                for (int e = 0; e < 4; e++) d2[nt][e] = 0.f;
#pragma unroll
            for (int ks = 0; ks < 4; ks++) {
                const int c = ks * 8 + ctg;
                unsigned ah[4], al[4];
                tfsplit(((const float*)sm.ex)[ex_idx(m0 + gid,     c)],     ah[0], al[0]);
                tfsplit(((const float*)sm.ex)[ex_idx(m0 + gid + 8, c)],     ah[1], al[1]);
                tfsplit(((const float*)sm.ex)[ex_idx(m0 + gid,     c + 4)], ah[2], al[2]);
                tfsplit(((const float*)sm.ex)[ex_idx(m0 + gid + 8, c + 4)], ah[3], al[3]);
#pragma unroll
                for (int nt = 0; nt < 2; nt++) {
                    unsigned bh[2], bl[2];
                    bh[0] = __float_as_uint(sm.w2hi[nt * 8 + gid][c]);
                    bh[1] = __float_as_uint(sm.w2hi[nt * 8 + gid][c + 4]);
                    bl[0] = __float_as_uint(sm.w2lo[nt * 8 + gid][c]);
                    bl[1] = __float_as_uint(sm.w2lo[nt * 8 + gid][c + 4]);
                    mma3x(d2[nt], ah, al, bh, bl);
                }
            }
            const int h0 = 2 * ctg, h1 = 2 * ctg + 1;
            const int base0 = h0 * SROWH + mt * SROWQ;
            const int base1 = h1 * SROWH + mt * SROWQ;
            sm.s[base0 + gid]     = d2[0][0] + sm.eb[h0];
            sm.s[base1 + gid]     = d2[0][1] + sm.eb[h1];
            sm.s[base0 + gid + 8] = d2[0][2] + sm.eb[h0];
            sm.s[base1 + gid + 8] = d2[0][3] + sm.eb[h1];
            sm.g[base0 + gid]     = 1.f / (1.f + __expf(-(d2[1][0] + sm.gb[h0])));
            sm.g[base1 + gid]     = 1.f / (1.f + __expf(-(d2[1][1] + sm.gb[h1])));
            sm.g[base0 + gid + 8] = 1.f / (1.f + __expf(-(d2[1][2] + sm.gb[h0])));
            sm.g[base1 + gid + 8] = 1.f / (1.f + __expf(-(d2[1][3] + sm.gb[h1])));
        }
        __syncthreads();

#pragma unroll
        for (int nt = 0; nt < 2; nt++) {
            const int kc = nt * 8 + 2 * ctg;
            u64* p01 = (u64*)&sm.s[w * SROWH + gid * SROWQ + kc];
            u64* p23 = (u64*)&sm.s[w * SROWH + (gid + 8) * SROWQ + kc];
            *p01 = fma2(pk2(ds[nt][0], ds[nt][1]), scl2, *p01);
            *p23 = fma2(pk2(ds[nt][2], ds[nt][3]), scl2, *p23);
        }
        __syncthreads();

        unsigned b3h[4][2], b3l[4][2];
#pragma unroll
        for (int nt = 0; nt < 4; nt++) {
            b3h[nt][0] = __float_as_uint(sm.eowhi[nt * 8 + gid][ctg]);
            b3h[nt][1] = __float_as_uint(sm.eowhi[nt * 8 + gid][ctg + 4]);
            b3l[nt][0] = __float_as_uint(sm.eowlo[nt * 8 + gid][ctg]);
            b3l[nt][1] = __float_as_uint(sm.eowlo[nt * 8 + gid][ctg + 4]);
        }
#pragma unroll
        for (int mtl = 0; mtl < 2; mtl++) {
            const int mt = 2 * w + mtl;
            unsigned ah[4], al[4];
            tfsplit(sm.s[ctg * SROWH + mt * SROWQ + gid],           ah[0], al[0]);
            tfsplit(sm.s[ctg * SROWH + mt * SROWQ + gid + 8],       ah[1], al[1]);
            tfsplit(sm.s[(ctg + 4) * SROWH + mt * SROWQ + gid],     ah[2], al[2]);
            tfsplit(sm.s[(ctg + 4) * SROWH + mt * SROWQ + gid + 8], ah[3], al[3]);
            float d3[4][4];
#pragma unroll
            for (int nt = 0; nt < 4; nt++) {
#pragma unroll
                for (int e = 0; e < 4; e++) d3[nt][e] = 0.f;
                mma3x(d3[nt], ah, al, b3h[nt], b3l[nt]);
            }
#pragma unroll
            for (int nt = 0; nt < 4; nt++) {
                const int col = nt * 8 + 2 * ctg;
                const int row = mt * 16 + gid;
                float o0 = d3[nt][0] + sm.eob[col];
                float o1 = d3[nt][1] + sm.eob[col + 1];
                float o2 = d3[nt][2] + sm.eob[col];
                float o3 = d3[nt][3] + sm.eob[col + 1];
                *(u64*)&((float*)sm.ex)[ex_idx(row, col)]     = pk2(o0, o1);
                *(u64*)&((float*)sm.ex)[ex_idx(row + 8, col)] = pk2(o2, o3);
            }
        }
        __syncthreads();

#pragma unroll
        for (int it = 0; it < 8; ++it) {
            float4 v4 = *(const float4*)&((const float*)sm.ex)
                            [ex_row[it] * 32 + ex_col4[it] * 4];
            *(float4*)&edge_out[((bL + q0 + ex_chunk[it]) * L_ + k0) * E_
                                + ex_w4[it] * 4] = v4;
        }

        if (i + 1 < NT) {
#pragma unroll
            for (int it = 0; it < 8; ++it)
                cp_async16(ex_base + ex_row[it] * 128 + ex_col4[it] * 16,
                           &edge_x[((bL + q0 + ex_chunk[it]) * L_ + k0 + KT) * E_
                                   + ex_w4[it] * 4]);
#pragma unroll
            for (int it = 0; it < 4; ++it) {
                int f4  = tid + it * 256;
                int row = f4 >> 6;
                int c   = (f4 & 63) * 4;
                cp_async16(s2u(&sm.k[row][c]),
                           &g_qkv[(bL + k0 + KT + row) * (3 * D_) + D_ + c]);
            }
        }
        cp_commit();

        if (lane < QT) {
            const int q = lane;
            float* srow = &sm.s[w * SROWH + q * SROWQ];
            float* grow = &sm.g[w * SROWH + q * SROWQ];
            float mold = sm.m[w][q];
            float tmax = -1e30f;
#pragma unroll
            for (int t4 = 0; t4 < 4; t4++) {
                float4 sv = *(const float4*)&srow[t4 * 4];
                tmax = fmaxf(tmax, fmaxf(fmaxf(sv.x, sv.y), fmaxf(sv.z, sv.w)));
            }
            float mnew = fmaxf(mold, tmax);
            float r    = __expf(mold - mnew);
            float zs   = 0.f;
#pragma unroll
            for (int t4 = 0; t4 < 4; t4++) {
                float4 sv = *(const float4*)&srow[t4 * 4];
                float4 gv = *(const float4*)&grow[t4 * 4];
                float p0 = __expf(sv.x - mnew);
                float p1 = __expf(sv.y - mnew);
                float p2 = __expf(sv.z - mnew);
                float p3 = __expf(sv.w - mnew);
                zs += (p0 + p1) + (p2 + p3);
                float4 o;
                o.x = p0 * gv.x; o.y = p1 * gv.y; o.z = p2 * gv.z; o.w = p3 * gv.w;
                *(float4*)&srow[t4 * 4] = o;
            }
            sm.z[w][q] = sm.z[w][q] * r + zs;
            sm.m[w][q] = mnew;
            sm.r[w][q] = r;
        }
        __syncwarp();
#pragma unroll
        for (int q = 0; q < QT; q++) {
            u64 a2 = mul2(acc2[q], dup2(sm.r[w][q]));
            const u64* prow = (const u64*)&sm.s[w * SROWH + q * SROWQ];
#pragma unroll
            for (int j = 0; j < 4; ++j) {
                a2 = fma2(prow[2 * j],     v2[2 * j],     a2);
                a2 = fma2(prow[2 * j + 1], v2[2 * j + 1], a2);
            }
            acc2[q] = a2;
        }
    }

#pragma unroll
    for (int q = 0; q < QT; q++) {
        g_aout[(bL + q0 + q) * D_ + w * HD_ + lane] = hsum2(acc2[q]) / sm.z[w][q];
    }
}

// ---------------------------------------------------------------------------
// kernel_launch
// ---------------------------------------------------------------------------
extern "C" void kernel_launch(void* const* d_in, const int* in_sizes, int n_in,
                              void* d_out, int out_size)
{
    const float* x       = (const float*)d_in[0];
    const float* edge_x  = (const float*)d_in[1];
    const float* in_w    = (const float*)d_in[2];
    const float* in_b    = (const float*)d_in[3];
    const float* out_w   = (const float*)d_in[4];
    const float* out_b   = (const float*)d_in[5];
    const float* e_w     = (const float*)d_in[6];
    const float* e_b     = (const float*)d_in[7];
    const float* g_w     = (const float*)d_in[8];
    const float* g_b     = (const float*)d_in[9];
    const float* eo_w    = (const float*)d_in[10];
    const float* eo_b    = (const float*)d_in[11];

    float* out0     = (float*)d_out;
    float* edge_out = out0 + (size_t)B_ * L_ * D_;

    float* qkv_ptr  = nullptr;
    float* aout_ptr = nullptr;
    cudaGetSymbolAddress((void**)&qkv_ptr,  g_qkv);
    cudaGetSymbolAddress((void**)&aout_ptr, g_aout);

    const int attn_smem = (int)sizeof(AttnSmem);
    const int gemm_smem = (int)sizeof(GemmSmem);
    cudaFuncSetAttribute(edge_attn_kernel,
                         cudaFuncAttributeMaxDynamicSharedMemorySize, attn_smem);
    cudaFuncSetAttribute(tf32_gemm_nt_bias,
                         cudaFuncAttributeMaxDynamicSharedMemorySize, gemm_smem);

    // 1) qkv = x @ in_proj_w^T + b
    tf32_gemm_nt_bias<<<dim3(3 * D_ / GBN, ROWS_ / GBM), 256, gemm_smem>>>(
        x, in_w, in_b, qkv_ptr, ROWS_, 3 * D_, D_);

    // 2) fused edge attention
    edge_attn_kernel<<<dim3(L_ / QT, B_), 256, attn_smem>>>(
        edge_x, e_w, e_b, g_w, g_b, eo_w, eo_b, edge_out);

    // 3) out = aout @ out_w^T + out_b
    tf32_gemm_nt_bias<<<dim3(D_ / GBN, ROWS_ / GBM), 256, gemm_smem>>>(
        aout_ptr, out_w, out_b, out0, ROWS_, D_, D_);
}